// round 6
// baseline (speedup 1.0000x reference)
#include <cuda_runtime.h>
#include <cuda_bf16.h>
#include <math.h>
#include <stdint.h>

#define Bq 4
#define Nv 12000
#define FN 24000
#define C 128
#define NNZ (48 * FN)     // 1,152,000
#define EPSV 1e-5f

#define RV (Bq * Nv)      // 48000 vertex rows
#define RF (Bq * FN)      // 96000 face rows

#define BINS 98304        // 96 * 1024 (covers 96000 rows)
#define EC_ROWS 64

// ---------------- scratch (device globals: allocation-free) ----------------
__device__ float  g_v[RV * C];
__device__ float  g_f[RF * C];
__device__ float  g_msg[RF * C];
__device__ double g_sum[256];
__device__ double g_sumsq[256];
__device__ __align__(16) float g_scale[256];
__device__ __align__(16) float g_shift[256];
__device__ double g_avgsum[Bq * C];
__device__ double g_masksum[Bq];
__device__ __align__(16) float g_bb[Bq * C];
__device__ __align__(16) __nv_bfloat16 g_Wt[32 * 2 * 32768]; // [conv][hi/lo][n=128][k=256]

// CSR build scratch
__device__ int    g_cnt[BINS];
__device__ int    g_incl[BINS];
__device__ int    g_bsum[96];
__device__ int    g_cursor[BINS];
__device__ int    g_startA[BINS + 1];
__device__ int    g_startB[BINS + 1];
__device__ float2 g_edgeA[NNZ];
__device__ float2 g_edgeB[NNZ];

__device__ __forceinline__ float elu_f(float x) {
    return x > 0.f ? x : expm1f(x);
}
__device__ __forceinline__ uint32_t pack_bf16(__nv_bfloat16 a, __nv_bfloat16 b) {
    return (uint32_t)__bfloat16_as_ushort(a) |
           ((uint32_t)__bfloat16_as_ushort(b) << 16);
}
__device__ __forceinline__ uint32_t smem_u32(const void* p) {
    uint32_t a;
    asm("{ .reg .u64 t; cvta.to.shared.u64 t, %1; cvt.u32.u64 %0, t; }"
        : "=r"(a) : "l"(p));
    return a;
}
__device__ __forceinline__ void ldsm_x4(uint32_t* r, uint32_t addr) {
    asm volatile("ldmatrix.sync.aligned.m8n8.x4.shared.b16 {%0,%1,%2,%3}, [%4];"
                 : "=r"(r[0]), "=r"(r[1]), "=r"(r[2]), "=r"(r[3]) : "r"(addr));
}
__device__ __forceinline__ void mma_bf16(float* d, const uint32_t* a,
                                         const uint32_t* b) {
    asm volatile(
        "mma.sync.aligned.m16n8k16.row.col.f32.bf16.bf16.f32 "
        "{%0,%1,%2,%3}, {%4,%5,%6,%7}, {%8,%9}, {%0,%1,%2,%3};"
        : "+f"(d[0]), "+f"(d[1]), "+f"(d[2]), "+f"(d[3])
        : "r"(a[0]), "r"(a[1]), "r"(a[2]), "r"(a[3]), "r"(b[0]), "r"(b[1]));
}

// ================= CSR build =================
__global__ void hist_kernel(const int* __restrict__ rows) {
    int i = blockIdx.x * blockDim.x + threadIdx.x;
    if (i < NNZ) atomicAdd(&g_cnt[rows[i]], 1);
}
__global__ void scan_block_kernel() {
    __shared__ int sd[1024];
    int t = threadIdx.x;
    int gid = blockIdx.x * 1024 + t;
    sd[t] = g_cnt[gid];
    __syncthreads();
    for (int off = 1; off < 1024; off <<= 1) {
        int add = (t >= off) ? sd[t - off] : 0;
        __syncthreads();
        sd[t] += add;
        __syncthreads();
    }
    g_incl[gid] = sd[t];
    if (t == 1023) g_bsum[blockIdx.x] = sd[1023];
}
__global__ void scan_top_kernel() {
    if (threadIdx.x == 0) {
        int run = 0;
        for (int b = 0; b < 96; b++) { int tt = g_bsum[b]; g_bsum[b] = run; run += tt; }
    }
}
__global__ void scan_finish_kernel(int* __restrict__ start) {
    int t = threadIdx.x;
    int gid = blockIdx.x * 1024 + t;
    int excl = g_incl[gid] - g_cnt[gid] + g_bsum[blockIdx.x];
    start[gid] = excl;
    g_cursor[gid] = excl;
    if (gid == BINS - 1) start[BINS] = excl + g_cnt[gid];
}
__global__ void fill_kernel(const int* __restrict__ rows,
                            const int* __restrict__ cols,
                            const float* __restrict__ vals,
                            float2* __restrict__ edges) {
    int i = blockIdx.x * blockDim.x + threadIdx.x;
    if (i >= NNZ) return;
    int pos = atomicAdd(&g_cursor[rows[i]], 1);
    edges[pos] = make_float2(vals[i], __int_as_float(cols[i]));
}

// ================= SpMM (CSR, atomic-free) =================
__global__ void spmm_kernel(const int* __restrict__ start,
                            const float2* __restrict__ edges,
                            const float* __restrict__ in, int inStride,
                            float* __restrict__ out, int outStride) {
    int t = threadIdx.x;
    int r = blockIdx.x * 4 + (t >> 5);
    int lane = t & 31;
    int b = lane >> 3, k4 = lane & 7;
    int s = start[r], e = start[r + 1];
    float4 acc = make_float4(0.f, 0.f, 0.f, 0.f);
    const float* inb = in + (size_t)b * inStride;
    for (int i = s; i < e; i++) {
        float2 ed = edges[i];
        int c = __float_as_int(ed.y);
        float4 q = *(const float4*)&inb[c * 32 + k4 * 4];
        acc.x = fmaf(ed.x, q.x, acc.x);
        acc.y = fmaf(ed.x, q.y, acc.y);
        acc.z = fmaf(ed.x, q.z, acc.z);
        acc.w = fmaf(ed.x, q.w, acc.w);
    }
    *(float4*)&out[(size_t)b * outStride + r * 32 + k4 * 4] = acc;
}

// ================= conv1 =================
__global__ void conv1_kernel(const float* __restrict__ in,
                             const float* __restrict__ W1,
                             const float* __restrict__ b1) {
    int idx = blockIdx.x * blockDim.x + threadIdx.x;
    if (idx >= RV * C) return;
    int r = idx >> 7, c = idx & 127;
    float x0 = in[r * 3 + 0], x1 = in[r * 3 + 1], x2 = in[r * 3 + 2];
    g_v[idx] = x0 * W1[c] + x1 * W1[128 + c] + x2 * W1[256 + c] + b1[c];
}

// ================= W prep: transpose + bf16 hi/lo split =========
__global__ void wprep_kernel(const float* __restrict__ rn_W) {
    int idx = blockIdx.x * blockDim.x + threadIdx.x;
    if (idx >= 32 * 32768) return;
    int cv = idx >> 15;
    int rem = idx & 32767;
    int k = rem >> 7, n = rem & 127;
    float w = rn_W[(size_t)cv * 32768 + k * 128 + n];
    __nv_bfloat16 hi = __float2bfloat16(w);
    __nv_bfloat16 lo = __float2bfloat16(w - __bfloat162float(hi));
    g_Wt[((size_t)cv * 2 + 0) * 32768 + n * 256 + k] = hi;
    g_Wt[((size_t)cv * 2 + 1) * 32768 + n * 256 + k] = lo;
}

// ================= stats over elu of two sources =================
__global__ void stats2_kernel(const float* __restrict__ x0,
                              const float* __restrict__ x1) {
    int c = threadIdx.x;
    int r0 = blockIdx.x * EC_ROWS;
    float s1 = 0.f, q1 = 0.f, s2 = 0.f, q2 = 0.f;
    for (int i = 0; i < EC_ROWS; i++) {
        int row = r0 + i;
        float xa = elu_f(x0[(size_t)row * 128 + c]);
        float xm = elu_f(x1[(size_t)row * 128 + c]);
        s1 += xa; q1 += xa * xa;
        s2 += xm; q2 += xm * xm;
    }
    atomicAdd(&g_sum[c], (double)s1);
    atomicAdd(&g_sumsq[c], (double)q1);
    atomicAdd(&g_sum[128 + c], (double)s2);
    atomicAdd(&g_sumsq[128 + c], (double)q2);
}

// ================= scale/shift prep =================
__global__ void prep_kernel(const float* __restrict__ gamma,
                            const float* __restrict__ beta,
                            int Cin, double invR) {
    int k = blockIdx.x * blockDim.x + threadIdx.x;
    if (k >= Cin) return;
    double mean = g_sum[k] * invR;
    double var  = g_sumsq[k] * invR - mean * mean;
    if (var < 0.0) var = 0.0;
    double a = (double)gamma[k] * rsqrt(var + (double)EPSV);
    g_scale[k] = (float)a;
    g_shift[k] = (float)((double)beta[k] - mean * a);
}

__global__ void prep_bcast_kernel(const float* __restrict__ gamma,
                                  const float* __restrict__ beta) {
    int k = threadIdx.x;
    double s = 0.0, sq = 0.0;
    for (int b = 0; b < Bq; b++) {
        float mf = (float)(g_avgsum[b * 128 + k] / g_masksum[b]);
        double m = (double)mf;
        s  += m * (double)Nv;
        sq += m * m * (double)Nv;
    }
    double invR = 1.0 / (double)RV;
    double mean = s * invR;
    double var  = sq * invR - mean * mean;
    if (var < 0.0) var = 0.0;
    double a = (double)gamma[128 + k] * rsqrt(var + (double)EPSV);
    g_scale[128 + k] = (float)a;
    g_shift[128 + k] = (float)((double)beta[128 + k] - mean * a);
}

__global__ void bb_kernel(const float* __restrict__ W) {
    int b = blockIdx.x, c = threadIdx.x;
    float acc = 0.f;
    for (int k = 0; k < 128; k++) {
        float af = (float)(g_avgsum[b * 128 + k] / g_masksum[b]);
        float xh = af * g_scale[128 + k] + g_shift[128 + k];
        acc += xh * W[(128 + k) * 128 + c];
    }
    g_bb[b * 128 + c] = acc;
}

// ================= mma.sync bf16x3 GEMM =================
// out[M,128] = (elu(A)*sc+sh)[M,KD] @ Wt^T + bias (+res) (+bb per batch)
// CTA: 128 rows x 128 cols, 8 warps (4M x 2N), warp tile 32x64.
// smem: As[buf][hi/lo][128][40] then Bs[buf][hi/lo][128][40], bf16 (stride 80B).
template <int KD, bool AVG>
__global__ void __launch_bounds__(256, 1) gemm_mma(
    const float* __restrict__ A0, const float* __restrict__ A1,
    const __nv_bfloat16* __restrict__ Wt,    // hi at +0, lo at +32768; [n][256]
    const float* __restrict__ bias,
    const float* __restrict__ res, float* __restrict__ out) {
    constexpr int BK = 32;
    constexpr int NCH = KD / BK;
    constexpr int LDS_ = 40;                     // b16 row stride
    constexpr int CB = 128 * LDS_ * 2;           // 10240 bytes per comp tile
    extern __shared__ char smem[];
    const uint32_t sbase = smem_u32(smem);       // As at 0, Bs at 4*CB

    const int tid = threadIdx.x;
    const int wid = tid >> 5, lane = tid & 31;
    const int wm = wid >> 1, wn = wid & 1;
    const int row0 = blockIdx.x * 128;

    const int lrow = tid >> 1;                   // 0..127 (A row / B n)
    const int lkh  = (tid & 1) * 16;             // 0 or 16

    float4 aReg[4];
    uint2  bReg[2][4];

    auto loadRegs = [&](int kc) {
        const float* src = (KD == 256 && kc >= 128)
            ? (A1 + (size_t)(row0 + lrow) * 128 + (kc - 128) + lkh)
            : (A0 + (size_t)(row0 + lrow) * 128 + kc + lkh);
#pragma unroll
        for (int j = 0; j < 4; j++) aReg[j] = *(const float4*)(src + j * 4);
#pragma unroll
        for (int comp = 0; comp < 2; comp++) {
            const __nv_bfloat16* ws = Wt + comp * 32768 + lrow * 256 + kc + lkh;
#pragma unroll
            for (int j = 0; j < 4; j++) bReg[comp][j] = *(const uint2*)(ws + j * 4);
        }
    };
    auto storeSmem = [&](int buf, int kc) {
        char* aHi = smem + (buf * 2 + 0) * CB + (size_t)(lrow * LDS_ + lkh) * 2;
        char* aLo = aHi + CB;
        char* bB  = smem + 4 * CB + (buf * 2 + 0) * CB
                  + (size_t)(lrow * LDS_ + lkh) * 2;
#pragma unroll
        for (int j = 0; j < 4; j++) {
            float xs[4] = {aReg[j].x, aReg[j].y, aReg[j].z, aReg[j].w};
            float4 s4 = *(const float4*)&g_scale[kc + lkh + j * 4];
            float4 h4 = *(const float4*)&g_shift[kc + lkh + j * 4];
            float sv[4] = {s4.x, s4.y, s4.z, s4.w};
            float hv[4] = {h4.x, h4.y, h4.z, h4.w};
            uint32_t hiw[2], low[2];
#pragma unroll
            for (int p = 0; p < 2; p++) {
                float x0 = fmaf(elu_f(xs[p * 2]),     sv[p * 2],     hv[p * 2]);
                float x1 = fmaf(elu_f(xs[p * 2 + 1]), sv[p * 2 + 1], hv[p * 2 + 1]);
                __nv_bfloat16 b0 = __float2bfloat16(x0);
                __nv_bfloat16 b1 = __float2bfloat16(x1);
                __nv_bfloat16 c0 = __float2bfloat16(x0 - __bfloat162float(b0));
                __nv_bfloat16 c1 = __float2bfloat16(x1 - __bfloat162float(b1));
                hiw[p] = pack_bf16(b0, b1);
                low[p] = pack_bf16(c0, c1);
            }
            *(uint2*)(aHi + j * 8) = make_uint2(hiw[0], hiw[1]);
            *(uint2*)(aLo + j * 8) = make_uint2(low[0], low[1]);
        }
#pragma unroll
        for (int comp = 0; comp < 2; comp++)
#pragma unroll
            for (int j = 0; j < 4; j++)
                *(uint2*)(bB + comp * CB + j * 8) = bReg[comp][j];
    };

    float acc[2][8][4];
#pragma unroll
    for (int mt = 0; mt < 2; mt++)
#pragma unroll
        for (int nt = 0; nt < 8; nt++)
#pragma unroll
            for (int q = 0; q < 4; q++) acc[mt][nt][q] = 0.f;

    loadRegs(0);
    storeSmem(0, 0);
    __syncthreads();

    const int lm = lane & 7;
    const int lsel = lane >> 3;

    for (int ch = 0; ch < NCH; ch++) {
        if (ch + 1 < NCH) loadRegs((ch + 1) * BK);
        int buf = ch & 1;
        uint32_t aHiB = sbase + (buf * 2 + 0) * CB;
        uint32_t aLoB = aHiB + CB;
        uint32_t bHiB = sbase + 4 * CB + (buf * 2 + 0) * CB;
        uint32_t bLoB = bHiB + CB;
#pragma unroll
        for (int ks = 0; ks < 2; ks++) {
            int k0 = ks * 16;
            uint32_t ah[2][4], al[2][4];
#pragma unroll
            for (int mt = 0; mt < 2; mt++) {
                int arow = wm * 32 + mt * 16 + lm + ((lsel & 1) ? 8 : 0);
                int acol = k0 + ((lsel >> 1) ? 8 : 0);
                uint32_t off = (uint32_t)(arow * LDS_ + acol) * 2;
                ldsm_x4(ah[mt], aHiB + off);
                ldsm_x4(al[mt], aLoB + off);
            }
            uint32_t bh[8][2], bl[8][2];
#pragma unroll
            for (int np = 0; np < 4; np++) {
                int brow = wn * 64 + np * 16 + lm + ((lsel >> 1) ? 8 : 0);
                int bcol = k0 + ((lsel & 1) ? 8 : 0);
                uint32_t off = (uint32_t)(brow * LDS_ + bcol) * 2;
                uint32_t t4[4];
                ldsm_x4(t4, bHiB + off);
                bh[np * 2][0] = t4[0]; bh[np * 2][1] = t4[1];
                bh[np * 2 + 1][0] = t4[2]; bh[np * 2 + 1][1] = t4[3];
                ldsm_x4(t4, bLoB + off);
                bl[np * 2][0] = t4[0]; bl[np * 2][1] = t4[1];
                bl[np * 2 + 1][0] = t4[2]; bl[np * 2 + 1][1] = t4[3];
            }
#pragma unroll
            for (int mt = 0; mt < 2; mt++)
#pragma unroll
                for (int nt = 0; nt < 8; nt++) {
                    mma_bf16(acc[mt][nt], ah[mt], bh[nt]);
                    mma_bf16(acc[mt][nt], ah[mt], bl[nt]);
                    mma_bf16(acc[mt][nt], al[mt], bh[nt]);
                }
        }
        if (ch + 1 < NCH) {
            storeSmem((ch + 1) & 1, (ch + 1) * BK);
            __syncthreads();
        }
    }

    // ---- epilogue ----
#pragma unroll
    for (int mt = 0; mt < 2; mt++) {
        int r1 = row0 + wm * 32 + mt * 16 + (lane >> 2);
        int r2 = r1 + 8;
        int rb1 = AVG ? (r1 / Nv) : 0;
        int rb2 = AVG ? (r2 / Nv) : 0;
#pragma unroll
        for (int nt = 0; nt < 8; nt++) {
            int cc = wn * 64 + nt * 8 + (lane & 3) * 2;
            float bx = bias[cc], by = bias[cc + 1];
            float o0 = acc[mt][nt][0] + bx, o1 = acc[mt][nt][1] + by;
            float o2 = acc[mt][nt][2] + bx, o3 = acc[mt][nt][3] + by;
            if (AVG) {
                o0 += g_bb[rb1 * 128 + cc];     o1 += g_bb[rb1 * 128 + cc + 1];
                o2 += g_bb[rb2 * 128 + cc];     o3 += g_bb[rb2 * 128 + cc + 1];
            }
            if (res) {
                float2 v1 = *(const float2*)&res[(size_t)r1 * 128 + cc];
                float2 v2 = *(const float2*)&res[(size_t)r2 * 128 + cc];
                o0 += v1.x; o1 += v1.y; o2 += v2.x; o3 += v2.y;
            }
            *(float2*)&out[(size_t)r1 * 128 + cc] = make_float2(o0, o1);
            *(float2*)&out[(size_t)r2 * 128 + cc] = make_float2(o2, o3);
        }
    }
}

// ================= avg-block: masked sums + stats ============
#define AVG_RPB 50
__global__ void avg_kernel(const float* __restrict__ x,
                           const float* __restrict__ mask) {
    const int blocksPerBatch = Nv / AVG_RPB;
    int b = blockIdx.x / blocksPerBatch;
    int n0 = (blockIdx.x % blocksPerBatch) * AVG_RPB;
    int c = threadIdx.x;
    float s = 0.f, ms = 0.f, s1 = 0.f, q1 = 0.f;
    for (int i = 0; i < AVG_RPB; i++) {
        int row = b * Nv + n0 + i;
        float mk = mask[row];
        float xe = elu_f(x[(size_t)row * 128 + c]);
        s  += mk * xe;
        s1 += xe;
        q1 += xe * xe;
        if (c == 0) ms += mk;
    }
    atomicAdd(&g_avgsum[b * 128 + c], (double)s);
    atomicAdd(&g_sum[c], (double)s1);
    atomicAdd(&g_sumsq[c], (double)q1);
    if (c == 0) atomicAdd(&g_masksum[b], (double)ms);
}

// ================= final conv =================
__global__ void fstats_kernel(const float* __restrict__ x, int rowsPerBlock) {
    int c = threadIdx.x;
    int r0 = blockIdx.x * rowsPerBlock;
    float s = 0.f, sq = 0.f;
    for (int r = r0; r < r0 + rowsPerBlock; r++) {
        float xv = elu_f(x[(size_t)r * 128 + c]);
        s += xv; sq += xv * xv;
    }
    atomicAdd(&g_sum[c], (double)s);
    atomicAdd(&g_sumsq[c], (double)sq);
}

__global__ void final_kernel(const float* __restrict__ f,
                             const float* __restrict__ W2,
                             const float* __restrict__ b2,
                             float* __restrict__ out) {
    int gwarp = (blockIdx.x * blockDim.x + threadIdx.x) >> 5;
    int lane = threadIdx.x & 31;
    if (gwarp >= RF) return;
    float s = 0.f;
#pragma unroll
    for (int j = 0; j < 4; j++) {
        int k = lane + j * 32;
        float xh = elu_f(f[(size_t)gwarp * 128 + k]) * g_scale[k] + g_shift[k];
        s += xh * W2[k];
    }
#pragma unroll
    for (int off = 16; off; off >>= 1) s += __shfl_down_sync(0xffffffffu, s, off);
    if (lane == 0) out[gwarp] = s + b2[0];
}

// ================= host orchestration =================
extern "C" void kernel_launch(void* const* d_in, const int* in_sizes, int n_in,
                              void* d_out, int out_size) {
    const float* inputs   = (const float*)d_in[0];
    const float* mask     = (const float*)d_in[1];
    const int*   Di_rows  = (const int*)d_in[2];
    const int*   Di_cols  = (const int*)d_in[3];
    const float* Di_vals  = (const float*)d_in[4];
    const int*   DiA_rows = (const int*)d_in[5];
    const int*   DiA_cols = (const int*)d_in[6];
    const float* DiA_vals = (const float*)d_in[7];
    const float* W1       = (const float*)d_in[8];
    const float* b1       = (const float*)d_in[9];
    const float* rn_gamma = (const float*)d_in[10];
    const float* rn_beta  = (const float*)d_in[11];
    const float* rn_W     = (const float*)d_in[12];
    const float* rn_b     = (const float*)d_in[13];
    const float* g2       = (const float*)d_in[14];
    const float* be2      = (const float*)d_in[15];
    const float* W2       = (const float*)d_in[16];
    const float* b2       = (const float*)d_in[17];
    float* out = (float*)d_out;

    float *v, *f, *msg;
    double *sum, *sumsq, *avgsum, *masksum;
    int *cnt, *startA, *startB;
    float2 *edgeA, *edgeB;
    __nv_bfloat16* Wt;
    cudaGetSymbolAddress((void**)&v, g_v);
    cudaGetSymbolAddress((void**)&f, g_f);
    cudaGetSymbolAddress((void**)&msg, g_msg);
    cudaGetSymbolAddress((void**)&sum, g_sum);
    cudaGetSymbolAddress((void**)&sumsq, g_sumsq);
    cudaGetSymbolAddress((void**)&avgsum, g_avgsum);
    cudaGetSymbolAddress((void**)&masksum, g_masksum);
    cudaGetSymbolAddress((void**)&cnt, g_cnt);
    cudaGetSymbolAddress((void**)&startA, g_startA);
    cudaGetSymbolAddress((void**)&startB, g_startB);
    cudaGetSymbolAddress((void**)&edgeA, g_edgeA);
    cudaGetSymbolAddress((void**)&edgeB, g_edgeB);
    cudaGetSymbolAddress((void**)&Wt, g_Wt);

    const int SMEM_GEMM = 8 * 10240;   // 81920 bytes
    cudaFuncSetAttribute(gemm_mma<256, false>,
                         cudaFuncAttributeMaxDynamicSharedMemorySize, SMEM_GEMM);
    cudaFuncSetAttribute(gemm_mma<128, true>,
                         cudaFuncAttributeMaxDynamicSharedMemorySize, SMEM_GEMM);

    auto clear_stats = [&]() {
        cudaMemsetAsync(sum, 0, 256 * sizeof(double), 0);
        cudaMemsetAsync(sumsq, 0, 256 * sizeof(double), 0);
    };
    auto build_csr = [&](const int* rows, const int* cols, const float* vals,
                         int* start, float2* edges) {
        cudaMemsetAsync(cnt, 0, BINS * sizeof(int), 0);
        hist_kernel<<<NNZ / 256, 256>>>(rows);
        scan_block_kernel<<<96, 1024>>>();
        scan_top_kernel<<<1, 32>>>();
        scan_finish_kernel<<<96, 1024>>>(start);
        fill_kernel<<<NNZ / 256, 256>>>(rows, cols, vals, edges);
    };

    build_csr(DiA_rows, DiA_cols, DiA_vals, startA, edgeA);
    build_csr(Di_rows, Di_cols, Di_vals, startB, edgeB);
    wprep_kernel<<<(32 * 32768) / 256, 256>>>(rn_W);

    conv1_kernel<<<(RV * C) / 256, 256>>>(inputs, W1, b1);
    cudaMemsetAsync(f, 0, (size_t)RF * C * sizeof(float), 0);

    for (int i = 0; i < 16; i++) {
        const float* Wb0 = rn_b + (size_t)i * 2 * 128;
        const float* gm0 = rn_gamma + (size_t)i * 2 * 256;
        const float* bt0 = rn_beta + (size_t)i * 2 * 256;
        const float* W0  = rn_W + (size_t)i * 2 * 256 * 128;  // fp32 (for bb)
        const __nv_bfloat16* wt0 = Wt + (size_t)(i * 2) * 65536;
        const __nv_bfloat16* wt1 = Wt + (size_t)(i * 2 + 1) * 65536;

        if ((i & 1) == 0) {
            // ---- dir block ----
            spmm_kernel<<<RV / 4, 128>>>(startA, edgeA, f, FN * C, msg, Nv * C);
            clear_stats();
            stats2_kernel<<<RV / EC_ROWS, 128>>>(v, msg);
            prep_kernel<<<1, 256>>>(gm0, bt0, 256, 1.0 / RV);
            gemm_mma<256, false><<<RV / 128, 256, SMEM_GEMM>>>(v, msg, wt0, Wb0, v, v);

            spmm_kernel<<<RF / 4, 128>>>(startB, edgeB, v, Nv * C, msg, FN * C);
            clear_stats();
            stats2_kernel<<<RF / EC_ROWS, 128>>>(f, msg);
            prep_kernel<<<1, 256>>>(gm0 + 256, bt0 + 256, 256, 1.0 / RF);
            gemm_mma<256, false><<<RF / 128, 256, SMEM_GEMM>>>(f, msg, wt1,
                                                               Wb0 + 128, nullptr, f);
        } else {
            // ---- avg block ----
            clear_stats();
            cudaMemsetAsync(avgsum, 0, Bq * C * sizeof(double), 0);
            cudaMemsetAsync(masksum, 0, Bq * sizeof(double), 0);
            avg_kernel<<<Bq * (Nv / AVG_RPB), 128>>>(v, mask);
            prep_kernel<<<1, 128>>>(gm0, bt0, 128, 1.0 / RV);
            prep_bcast_kernel<<<1, 128>>>(gm0, bt0);
            bb_kernel<<<Bq, 128>>>(W0);
            gemm_mma<128, true><<<RV / 128, 256, SMEM_GEMM>>>(v, nullptr, wt0, Wb0,
                                                              nullptr, msg);

            clear_stats();
            cudaMemsetAsync(avgsum, 0, Bq * C * sizeof(double), 0);
            cudaMemsetAsync(masksum, 0, Bq * sizeof(double), 0);
            avg_kernel<<<Bq * (Nv / AVG_RPB), 128>>>(msg, mask);
            prep_kernel<<<1, 128>>>(gm0 + 256, bt0 + 256, 128, 1.0 / RV);
            prep_bcast_kernel<<<1, 128>>>(gm0 + 256, bt0 + 256);
            bb_kernel<<<Bq, 128>>>(W0 + 256 * 128);
            gemm_mma<128, true><<<RV / 128, 256, SMEM_GEMM>>>(msg, nullptr, wt1,
                                                              Wb0 + 128, v, v);
        }
    }

    // final conv
    clear_stats();
    fstats_kernel<<<RF / 128, 128>>>(f, 128);
    prep_kernel<<<1, 128>>>(g2, be2, 128, 1.0 / RF);
    final_kernel<<<(RF + 7) / 8, 256>>>(f, W2, b2, out);
}

// round 7
// speedup vs baseline: 1.3424x; 1.3424x over previous
#include <cuda_runtime.h>
#include <math.h>
#include <stdint.h>

#define Bq 4
#define Nv 12000
#define FN 24000
#define C 128
#define NNZ (48 * FN)     // 1,152,000
#define EPSV 1e-5f

#define RV (Bq * Nv)      // 48000 vertex rows
#define RF (Bq * FN)      // 96000 face rows

#define BINS 98304        // 96 * 1024 (covers 96000 rows)
#define EC_ROWS 64

// ---------------- scratch (device globals: allocation-free) ----------------
__device__ float  g_v[RV * C];
__device__ float  g_f[RF * C];
__device__ float  g_msg[RF * C];
__device__ double g_stats[512];         // [0,256)=sum, [256,512)=sumsq
__device__ __align__(16) float g_scale[256];
__device__ __align__(16) float g_shift[256];
__device__ double g_avgms[Bq * C + Bq]; // [0,512)=avgsum, [512,516)=masksum
__device__ __align__(16) float g_bb[Bq * C];

// CSR build scratch
__device__ int    g_cnt[BINS];
__device__ int    g_incl[BINS];
__device__ int    g_bsum[96];
__device__ int    g_cursor[BINS];
__device__ int    g_startA[BINS + 1];   // DiA: 48000 rows
__device__ int    g_startB[BINS + 1];   // Di : 96000 rows
__device__ float2 g_edgeA[NNZ];         // (val, bitcast col), row-sorted
__device__ float2 g_edgeB[NNZ];

__device__ __forceinline__ float elu_f(float x) {
    return x > 0.f ? x : expm1f(x);
}

// ================= CSR build =================
__global__ void hist_kernel(const int* __restrict__ rows) {
    int i = blockIdx.x * blockDim.x + threadIdx.x;
    if (i < NNZ) atomicAdd(&g_cnt[rows[i]], 1);
}

__global__ void scan_block_kernel() {
    __shared__ int sd[1024];
    int t = threadIdx.x;
    int gid = blockIdx.x * 1024 + t;
    sd[t] = g_cnt[gid];
    __syncthreads();
    for (int off = 1; off < 1024; off <<= 1) {
        int add = (t >= off) ? sd[t - off] : 0;
        __syncthreads();
        sd[t] += add;
        __syncthreads();
    }
    g_incl[gid] = sd[t];
    if (t == 1023) g_bsum[blockIdx.x] = sd[1023];
}

__global__ void scan_top_kernel() {
    if (threadIdx.x == 0) {
        int run = 0;
        for (int b = 0; b < 96; b++) { int tt = g_bsum[b]; g_bsum[b] = run; run += tt; }
    }
}

__global__ void scan_finish_kernel(int* __restrict__ start) {
    int t = threadIdx.x;
    int gid = blockIdx.x * 1024 + t;
    int excl = g_incl[gid] - g_cnt[gid] + g_bsum[blockIdx.x];
    start[gid] = excl;
    g_cursor[gid] = excl;
    if (gid == BINS - 1) start[BINS] = excl + g_cnt[gid];
}

__global__ void fill_kernel(const int* __restrict__ rows,
                            const int* __restrict__ cols,
                            const float* __restrict__ vals,
                            float2* __restrict__ edges) {
    int i = blockIdx.x * blockDim.x + threadIdx.x;
    if (i >= NNZ) return;
    int pos = atomicAdd(&g_cursor[rows[i]], 1);
    edges[pos] = make_float2(vals[i], __int_as_float(cols[i]));
}

// ================= SpMM (CSR, atomic-free) =================
// out[b, r*32 + k] = sum_{e in row r} val_e * in[b, col_e*32 + k]
__global__ void spmm_kernel(const int* __restrict__ start,
                            const float2* __restrict__ edges,
                            const float* __restrict__ in, int inStride,
                            float* __restrict__ out, int outStride) {
    int t = threadIdx.x;
    int r = blockIdx.x * 4 + (t >> 5);
    int lane = t & 31;
    int b = lane >> 3, k4 = lane & 7;
    int s = start[r], e = start[r + 1];
    float4 acc = make_float4(0.f, 0.f, 0.f, 0.f);
    const float* inb = in + (size_t)b * inStride;
    for (int i = s; i < e; i++) {
        float2 ed = edges[i];
        int c = __float_as_int(ed.y);
        float4 q = *(const float4*)&inb[c * 32 + k4 * 4];
        acc.x = fmaf(ed.x, q.x, acc.x);
        acc.y = fmaf(ed.x, q.y, acc.y);
        acc.z = fmaf(ed.x, q.z, acc.z);
        acc.w = fmaf(ed.x, q.w, acc.w);
    }
    *(float4*)&out[(size_t)b * outStride + r * 32 + k4 * 4] = acc;
}

// ================= conv1 =================
__global__ void conv1_kernel(const float* __restrict__ in,
                             const float* __restrict__ W1,
                             const float* __restrict__ b1) {
    int idx = blockIdx.x * blockDim.x + threadIdx.x;
    if (idx >= RV * C) return;
    int r = idx >> 7, c = idx & 127;
    float x0 = in[r * 3 + 0], x1 = in[r * 3 + 1], x2 = in[r * 3 + 2];
    g_v[idx] = x0 * W1[c] + x1 * W1[128 + c] + x2 * W1[256 + c] + b1[c];
}

// ================= stats over elu of two sources (dir blocks) =================
__global__ void stats2_kernel(const float* __restrict__ x0,
                              const float* __restrict__ x1) {
    int c = threadIdx.x;                      // 128
    int r0 = blockIdx.x * EC_ROWS;
    float s1 = 0.f, q1 = 0.f, s2 = 0.f, q2 = 0.f;
    for (int i = 0; i < EC_ROWS; i++) {
        int row = r0 + i;
        float xa = elu_f(x0[(size_t)row * 128 + c]);
        float xm = elu_f(x1[(size_t)row * 128 + c]);
        s1 += xa; q1 += xa * xa;
        s2 += xm; q2 += xm * xm;
    }
    atomicAdd(&g_stats[c], (double)s1);
    atomicAdd(&g_stats[256 + c], (double)q1);
    atomicAdd(&g_stats[128 + c], (double)s2);
    atomicAdd(&g_stats[384 + c], (double)q2);
}

// ================= scale/shift prep =================
__global__ void prep_kernel(const float* __restrict__ gamma,
                            const float* __restrict__ beta,
                            int Cin, double invR) {
    int k = blockIdx.x * blockDim.x + threadIdx.x;
    if (k >= Cin) return;
    double mean = g_stats[k] * invR;
    double var  = g_stats[256 + k] * invR - mean * mean;
    if (var < 0.0) var = 0.0;
    double a = (double)gamma[k] * rsqrt(var + (double)EPSV);
    g_scale[k] = (float)a;
    g_shift[k] = (float)((double)beta[k] - mean * a);
}

__global__ void prep_bcast_kernel(const float* __restrict__ gamma,
                                  const float* __restrict__ beta) {
    int k = threadIdx.x;                      // 128
    double s = 0.0, sq = 0.0;
    for (int b = 0; b < Bq; b++) {
        float mf = (float)(g_avgms[b * 128 + k] / g_avgms[512 + b]);
        double m = (double)mf;
        s  += m * (double)Nv;
        sq += m * m * (double)Nv;
    }
    double invR = 1.0 / (double)RV;
    double mean = s * invR;
    double var  = sq * invR - mean * mean;
    if (var < 0.0) var = 0.0;
    double a = (double)gamma[128 + k] * rsqrt(var + (double)EPSV);
    g_scale[128 + k] = (float)a;
    g_shift[128 + k] = (float)((double)beta[128 + k] - mean * a);
}

// per-batch folded bias from broadcast channels: bb[b][c] = sum_k xh2[b,k]*W[128+k][c]
__global__ void bb_kernel(const float* __restrict__ W) {
    int b = blockIdx.x, c = threadIdx.x;
    float acc = 0.f;
    for (int k = 0; k < 128; k++) {
        float af = (float)(g_avgms[b * 128 + k] / g_avgms[512 + b]);
        float xh = af * g_scale[128 + k] + g_shift[128 + k];
        acc += xh * W[(128 + k) * 128 + c];
    }
    g_bb[b * 128 + c] = acc;
}

// ================= SIMT GEMM (conflict-free, occ-2, single-sync) =================
// out[M,128] = (elu(A)*scale+shift)[M,KD] @ W[KD,128] + bias (+ res) (+ bb per batch)
// KD=256: A channels 0..127 from A0, 128..255 from A1.
// Thread (ty,tx) owns rows {ty*4+il, ty*4+64+il}, cols {tx*4+jl, tx*4+64+jl}.
template <int KD, bool AVG>
__global__ void __launch_bounds__(256, 2) gemm_kernel(
    const float* __restrict__ A0, const float* __restrict__ A1,
    const float* __restrict__ W, const float* __restrict__ bias,
    const float* __restrict__ res, float* __restrict__ out) {
    __shared__ float As[2][16][128];
    __shared__ float Bs[2][16][128];
    __shared__ float sc[KD], sh[KD];
    const int tid = threadIdx.x;
    const int row0 = blockIdx.x * 128;

    if (tid < KD) { sc[tid] = g_scale[tid]; sh[tid] = g_shift[tid]; }

    const int arow = tid >> 1;            // 0..127
    const int akb  = (tid & 1) * 8;       // 0 or 8
    const int bkr  = tid >> 4;            // 0..15
    const int bcx  = (tid & 15) * 4;      // 0..60
    const int ty = tid >> 4, tx = tid & 15;
    const int NCH = KD / 16;

    float4 areg[2], breg[2];

    auto loadAB = [&](int k0) {
#pragma unroll
        for (int q = 0; q < 2; q++) {
            int k = k0 + akb + q * 4;
            const float* src;
            if (KD == 256 && k >= 128)
                src = A1 + (size_t)(row0 + arow) * 128 + (k - 128);
            else
                src = A0 + (size_t)(row0 + arow) * 128 + k;
            areg[q] = *(const float4*)src;
            breg[q] = *(const float4*)&W[(size_t)(k0 + bkr) * 128 + bcx + q * 64];
        }
    };
    auto storeAB = [&](int buf, int k0) {
#pragma unroll
        for (int q = 0; q < 2; q++) {
            float vv[4] = {areg[q].x, areg[q].y, areg[q].z, areg[q].w};
#pragma unroll
            for (int j = 0; j < 4; j++) {
                int kl = akb + q * 4 + j;
                float x = vv[j];
                x = x > 0.f ? x : expm1f(x);
                As[buf][kl][arow] = fmaf(x, sc[k0 + kl], sh[k0 + kl]);
            }
            *(float4*)&Bs[buf][bkr][bcx + q * 64] = breg[q];
        }
    };

    float acc[8][8];
#pragma unroll
    for (int i = 0; i < 8; i++)
#pragma unroll
        for (int j = 0; j < 8; j++) acc[i][j] = 0.f;

    loadAB(0);
    __syncthreads();            // sc/sh ready
    storeAB(0, 0);
    __syncthreads();

    for (int ch = 0; ch < NCH; ch++) {
        int nxt = ch + 1;
        if (nxt < NCH) loadAB(nxt * 16);
        int buf = ch & 1;
#pragma unroll
        for (int kk = 0; kk < 16; kk++) {
            float4 a0 = *(const float4*)&As[buf][kk][ty * 4];
            float4 a1 = *(const float4*)&As[buf][kk][ty * 4 + 64];
            float4 b0 = *(const float4*)&Bs[buf][kk][tx * 4];
            float4 b1 = *(const float4*)&Bs[buf][kk][tx * 4 + 64];
            float av[8] = {a0.x, a0.y, a0.z, a0.w, a1.x, a1.y, a1.z, a1.w};
            float bv[8] = {b0.x, b0.y, b0.z, b0.w, b1.x, b1.y, b1.z, b1.w};
#pragma unroll
            for (int i = 0; i < 8; i++)
#pragma unroll
                for (int j = 0; j < 8; j++)
                    acc[i][j] = fmaf(av[i], bv[j], acc[i][j]);
        }
        if (nxt < NCH) {
            // store targets the OTHER buffer — no pre-store sync needed;
            // post-store sync fences both the new buffer and cross-iter reuse.
            storeAB(nxt & 1, nxt * 16);
            __syncthreads();
        }
    }

#pragma unroll
    for (int i = 0; i < 8; i++) {
        int r = row0 + ty * 4 + (i & 3) + (i >> 2) * 64;
        int rb = AVG ? (r / Nv) : 0;
#pragma unroll
        for (int jh = 0; jh < 2; jh++) {
            int c = tx * 4 + jh * 64;
            float4 o;
            o.x = acc[i][jh * 4 + 0] + bias[c + 0];
            o.y = acc[i][jh * 4 + 1] + bias[c + 1];
            o.z = acc[i][jh * 4 + 2] + bias[c + 2];
            o.w = acc[i][jh * 4 + 3] + bias[c + 3];
            if (AVG) {
                const float4 bv = *(const float4*)&g_bb[rb * 128 + c];
                o.x += bv.x; o.y += bv.y; o.z += bv.z; o.w += bv.w;
            }
            if (res) {
                const float4 rv = *(const float4*)&res[(size_t)r * 128 + c];
                o.x += rv.x; o.y += rv.y; o.z += rv.z; o.w += rv.w;
            }
            *(float4*)&out[(size_t)r * 128 + c] = o;
        }
    }
}

// ================= avg-block: masked sums + stats ============
#define AVG_RPB 50
__global__ void avg_kernel(const float* __restrict__ x,
                           const float* __restrict__ mask) {
    const int blocksPerBatch = Nv / AVG_RPB;   // 240
    int b = blockIdx.x / blocksPerBatch;
    int n0 = (blockIdx.x % blocksPerBatch) * AVG_RPB;
    int c = threadIdx.x;                       // 128
    float s = 0.f, ms = 0.f, s1 = 0.f, q1 = 0.f;
    for (int i = 0; i < AVG_RPB; i++) {
        int row = b * Nv + n0 + i;
        float mk = mask[row];
        float xe = elu_f(x[(size_t)row * 128 + c]);
        s  += mk * xe;
        s1 += xe;
        q1 += xe * xe;
        if (c == 0) ms += mk;
    }
    atomicAdd(&g_avgms[b * 128 + c], (double)s);
    atomicAdd(&g_stats[c], (double)s1);
    atomicAdd(&g_stats[256 + c], (double)q1);
    if (c == 0) atomicAdd(&g_avgms[512 + b], (double)ms);
}

// ================= final conv =================
__global__ void fstats_kernel(const float* __restrict__ x, int rowsPerBlock) {
    int c = threadIdx.x;                       // 128
    int r0 = blockIdx.x * rowsPerBlock;
    float s = 0.f, sq = 0.f;
    for (int r = r0; r < r0 + rowsPerBlock; r++) {
        float xv = elu_f(x[(size_t)r * 128 + c]);
        s += xv; sq += xv * xv;
    }
    atomicAdd(&g_stats[c], (double)s);
    atomicAdd(&g_stats[256 + c], (double)sq);
}

__global__ void final_kernel(const float* __restrict__ f,
                             const float* __restrict__ W2,
                             const float* __restrict__ b2,
                             float* __restrict__ out) {
    int gwarp = (blockIdx.x * blockDim.x + threadIdx.x) >> 5;
    int lane = threadIdx.x & 31;
    if (gwarp >= RF) return;
    float s = 0.f;
#pragma unroll
    for (int j = 0; j < 4; j++) {
        int k = lane + j * 32;
        float xh = elu_f(f[(size_t)gwarp * 128 + k]) * g_scale[k] + g_shift[k];
        s += xh * W2[k];
    }
#pragma unroll
    for (int off = 16; off; off >>= 1) s += __shfl_down_sync(0xffffffffu, s, off);
    if (lane == 0) out[gwarp] = s + b2[0];
}

// ================= host orchestration =================
extern "C" void kernel_launch(void* const* d_in, const int* in_sizes, int n_in,
                              void* d_out, int out_size) {
    const float* inputs   = (const float*)d_in[0];
    const float* mask     = (const float*)d_in[1];
    const int*   Di_rows  = (const int*)d_in[2];
    const int*   Di_cols  = (const int*)d_in[3];
    const float* Di_vals  = (const float*)d_in[4];
    const int*   DiA_rows = (const int*)d_in[5];
    const int*   DiA_cols = (const int*)d_in[6];
    const float* DiA_vals = (const float*)d_in[7];
    const float* W1       = (const float*)d_in[8];
    const float* b1       = (const float*)d_in[9];
    const float* rn_gamma = (const float*)d_in[10];
    const float* rn_beta  = (const float*)d_in[11];
    const float* rn_W     = (const float*)d_in[12];
    const float* rn_b     = (const float*)d_in[13];
    const float* g2       = (const float*)d_in[14];
    const float* be2      = (const float*)d_in[15];
    const float* W2       = (const float*)d_in[16];
    const float* b2       = (const float*)d_in[17];
    float* out = (float*)d_out;

    float *v, *f, *msg;
    double *stats, *avgms;
    int *cnt, *startA, *startB;
    float2 *edgeA, *edgeB;
    cudaGetSymbolAddress((void**)&v, g_v);
    cudaGetSymbolAddress((void**)&f, g_f);
    cudaGetSymbolAddress((void**)&msg, g_msg);
    cudaGetSymbolAddress((void**)&stats, g_stats);
    cudaGetSymbolAddress((void**)&avgms, g_avgms);
    cudaGetSymbolAddress((void**)&cnt, g_cnt);
    cudaGetSymbolAddress((void**)&startA, g_startA);
    cudaGetSymbolAddress((void**)&startB, g_startB);
    cudaGetSymbolAddress((void**)&edgeA, g_edgeA);
    cudaGetSymbolAddress((void**)&edgeB, g_edgeB);

    auto clear_stats = [&]() {
        cudaMemsetAsync(stats, 0, 512 * sizeof(double), 0);
    };
    auto build_csr = [&](const int* rows, const int* cols, const float* vals,
                         int* start, float2* edges) {
        cudaMemsetAsync(cnt, 0, BINS * sizeof(int), 0);
        hist_kernel<<<NNZ / 256, 256>>>(rows);
        scan_block_kernel<<<96, 1024>>>();
        scan_top_kernel<<<1, 32>>>();
        scan_finish_kernel<<<96, 1024>>>(start);
        fill_kernel<<<NNZ / 256, 256>>>(rows, cols, vals, edges);
    };

    // CSR for both sparse operators
    build_csr(DiA_rows, DiA_cols, DiA_vals, startA, edgeA);
    build_csr(Di_rows, Di_cols, Di_vals, startB, edgeB);

    // conv1 + init f = 0
    conv1_kernel<<<(RV * C) / 256, 256>>>(inputs, W1, b1);
    cudaMemsetAsync(f, 0, (size_t)RF * C * sizeof(float), 0);

    for (int i = 0; i < 16; i++) {
        const float* W0  = rn_W + (size_t)i * 2 * 256 * 128;
        const float* Wb0 = rn_b + (size_t)i * 2 * 128;
        const float* gm0 = rn_gamma + (size_t)i * 2 * 256;
        const float* bt0 = rn_beta + (size_t)i * 2 * 256;

        if ((i & 1) == 0) {
            // ---- dir block ----
            spmm_kernel<<<RV / 4, 128>>>(startA, edgeA, f, FN * C, msg, Nv * C);
            clear_stats();
            stats2_kernel<<<RV / EC_ROWS, 128>>>(v, msg);
            prep_kernel<<<1, 256>>>(gm0, bt0, 256, 1.0 / RV);
            gemm_kernel<256, false><<<RV / 128, 256>>>(v, msg, W0, Wb0, v, v);

            spmm_kernel<<<RF / 4, 128>>>(startB, edgeB, v, Nv * C, msg, FN * C);
            clear_stats();
            stats2_kernel<<<RF / EC_ROWS, 128>>>(f, msg);
            prep_kernel<<<1, 256>>>(gm0 + 256, bt0 + 256, 256, 1.0 / RF);
            gemm_kernel<256, false><<<RF / 128, 256>>>(f, msg, W0 + 256 * 128,
                                                       Wb0 + 128, nullptr, f);
        } else {
            // ---- avg block ----
            clear_stats();
            cudaMemsetAsync(avgms, 0, (Bq * C + Bq) * sizeof(double), 0);
            avg_kernel<<<Bq * (Nv / AVG_RPB), 128>>>(v, mask);
            prep_kernel<<<1, 128>>>(gm0, bt0, 128, 1.0 / RV);
            prep_bcast_kernel<<<1, 128>>>(gm0, bt0);
            bb_kernel<<<Bq, 128>>>(W0);
            gemm_kernel<128, true><<<RV / 128, 256>>>(v, nullptr, W0, Wb0,
                                                      nullptr, msg);

            clear_stats();
            cudaMemsetAsync(avgms, 0, (Bq * C + Bq) * sizeof(double), 0);
            avg_kernel<<<Bq * (Nv / AVG_RPB), 128>>>(msg, mask);
            prep_kernel<<<1, 128>>>(gm0 + 256, bt0 + 256, 128, 1.0 / RV);
            prep_bcast_kernel<<<1, 128>>>(gm0 + 256, bt0 + 256);
            bb_kernel<<<Bq, 128>>>(W0 + 256 * 128);
            gemm_kernel<128, true><<<RV / 128, 256>>>(msg, nullptr,
                                                      W0 + 256 * 128, Wb0 + 128,
                                                      v, v);
        }
    }

    // final conv
    clear_stats();
    fstats_kernel<<<RF / 128, 128>>>(f, 128);
    prep_kernel<<<1, 128>>>(g2, be2, 128, 1.0 / RF);
    final_kernel<<<(RF + 7) / 8, 256>>>(f, W2, b2, out);
}

// round 8
// speedup vs baseline: 1.5911x; 1.1852x over previous
#include <cuda_runtime.h>
#include <math.h>
#include <stdint.h>

#define Bq 4
#define Nv 12000
#define FN 24000
#define C 128
#define NNZ (48 * FN)     // 1,152,000
#define EPSV 1e-5f

#define RV (Bq * Nv)      // 48000 vertex rows
#define RF (Bq * FN)      // 96000 face rows

#define BINS 98304        // 96 * 1024 (covers 96000 rows)
#define EC_ROWS 64

// ---------------- scratch (device globals: allocation-free) ----------------
__device__ float  g_v[RV * C];
__device__ float  g_f[RF * C];
__device__ float  g_msg[RF * C];
__device__ double g_stats[512];         // [0,256)=sum, [256,512)=sumsq  (self-zeroing)
__device__ __align__(16) float g_scale[256];
__device__ __align__(16) float g_shift[256];
__device__ double g_avgms[Bq * C + Bq]; // [0,512)=avgsum, [512,516)=masksum (self-zeroing)
__device__ __align__(16) float g_bb[Bq * C];

// CSR build scratch
__device__ int    g_cnt[BINS];
__device__ int    g_incl[BINS];
__device__ int    g_bsum[96];
__device__ int    g_cursor[BINS];
__device__ int    g_startA[BINS + 1];   // DiA: 48000 rows
__device__ int    g_startB[BINS + 1];   // Di : 96000 rows
__device__ float2 g_edgeA[NNZ];         // (val, bitcast col), row-sorted
__device__ float2 g_edgeB[NNZ];

__device__ __forceinline__ float elu_f(float x) {
    return x > 0.f ? x : expm1f(x);
}

// ================= CSR build =================
__global__ void hist_kernel(const int* __restrict__ rows) {
    int i = blockIdx.x * blockDim.x + threadIdx.x;
    if (i < NNZ) atomicAdd(&g_cnt[rows[i]], 1);
}

__global__ void scan_block_kernel() {
    __shared__ int sd[1024];
    int t = threadIdx.x;
    int gid = blockIdx.x * 1024 + t;
    sd[t] = g_cnt[gid];
    __syncthreads();
    for (int off = 1; off < 1024; off <<= 1) {
        int add = (t >= off) ? sd[t - off] : 0;
        __syncthreads();
        sd[t] += add;
        __syncthreads();
    }
    g_incl[gid] = sd[t];
    if (t == 1023) g_bsum[blockIdx.x] = sd[1023];
}

__global__ void scan_top_kernel() {
    if (threadIdx.x == 0) {
        int run = 0;
        for (int b = 0; b < 96; b++) { int tt = g_bsum[b]; g_bsum[b] = run; run += tt; }
    }
}

__global__ void scan_finish_kernel(int* __restrict__ start) {
    int t = threadIdx.x;
    int gid = blockIdx.x * 1024 + t;
    int excl = g_incl[gid] - g_cnt[gid] + g_bsum[blockIdx.x];
    start[gid] = excl;
    g_cursor[gid] = excl;
    if (gid == BINS - 1) start[BINS] = excl + g_cnt[gid];
}

__global__ void fill_kernel(const int* __restrict__ rows,
                            const int* __restrict__ cols,
                            const float* __restrict__ vals,
                            float2* __restrict__ edges) {
    int i = blockIdx.x * blockDim.x + threadIdx.x;
    if (i >= NNZ) return;
    int pos = atomicAdd(&g_cursor[rows[i]], 1);
    edges[pos] = make_float2(vals[i], __int_as_float(cols[i]));
}

// ================= SpMM (CSR, atomic-free) =================
__global__ void spmm_kernel(const int* __restrict__ start,
                            const float2* __restrict__ edges,
                            const float* __restrict__ in, int inStride,
                            float* __restrict__ out, int outStride) {
    int t = threadIdx.x;
    int r = blockIdx.x * 4 + (t >> 5);
    int lane = t & 31;
    int b = lane >> 3, k4 = lane & 7;
    int s = start[r], e = start[r + 1];
    float4 acc = make_float4(0.f, 0.f, 0.f, 0.f);
    const float* inb = in + (size_t)b * inStride;
    for (int i = s; i < e; i++) {
        float2 ed = edges[i];
        int c = __float_as_int(ed.y);
        float4 q = *(const float4*)&inb[c * 32 + k4 * 4];
        acc.x = fmaf(ed.x, q.x, acc.x);
        acc.y = fmaf(ed.x, q.y, acc.y);
        acc.z = fmaf(ed.x, q.z, acc.z);
        acc.w = fmaf(ed.x, q.w, acc.w);
    }
    *(float4*)&out[(size_t)b * outStride + r * 32 + k4 * 4] = acc;
}

// ================= conv1 =================
__global__ void conv1_kernel(const float* __restrict__ in,
                             const float* __restrict__ W1,
                             const float* __restrict__ b1) {
    int idx = blockIdx.x * blockDim.x + threadIdx.x;
    if (idx >= RV * C) return;
    int r = idx >> 7, c = idx & 127;
    float x0 = in[r * 3 + 0], x1 = in[r * 3 + 1], x2 = in[r * 3 + 2];
    g_v[idx] = x0 * W1[c] + x1 * W1[128 + c] + x2 * W1[256 + c] + b1[c];
}

// ================= stats over elu of two sources (dir blocks) =================
__global__ void stats2_kernel(const float* __restrict__ x0,
                              const float* __restrict__ x1) {
    int c = threadIdx.x;                      // 128
    int r0 = blockIdx.x * EC_ROWS;
    float s1 = 0.f, q1 = 0.f, s2 = 0.f, q2 = 0.f;
    for (int i = 0; i < EC_ROWS; i++) {
        int row = r0 + i;
        float xa = elu_f(x0[(size_t)row * 128 + c]);
        float xm = elu_f(x1[(size_t)row * 128 + c]);
        s1 += xa; q1 += xa * xa;
        s2 += xm; q2 += xm * xm;
    }
    atomicAdd(&g_stats[c], (double)s1);
    atomicAdd(&g_stats[256 + c], (double)q1);
    atomicAdd(&g_stats[128 + c], (double)s2);
    atomicAdd(&g_stats[384 + c], (double)q2);
}

// ============ scale/shift prep (dir + final); zeroes consumed stats ============
__global__ void prep_kernel(const float* __restrict__ gamma,
                            const float* __restrict__ beta,
                            int Cin, double invR) {
    int k = blockIdx.x * blockDim.x + threadIdx.x;
    if (k >= Cin) return;
    double mean = g_stats[k] * invR;
    double var  = g_stats[256 + k] * invR - mean * mean;
    if (var < 0.0) var = 0.0;
    double a = (double)gamma[k] * rsqrt(var + (double)EPSV);
    g_scale[k] = (float)a;
    g_shift[k] = (float)((double)beta[k] - mean * a);
    g_stats[k] = 0.0;
    g_stats[256 + k] = 0.0;
}

// ===== avg-block prep: scale/shift (normal + analytic broadcast) + bb fold =====
// one block, 128 threads; zeroes consumed g_stats and g_avgms
__global__ void prep_avg_kernel(const float* __restrict__ gamma,
                                const float* __restrict__ beta,
                                const float* __restrict__ W) {
    __shared__ float xh2[Bq][128];
    int k = threadIdx.x;                      // 128
    const double invR = 1.0 / (double)RV;

    // normal channels [0,128) from accumulated stats
    {
        double mean = g_stats[k] * invR;
        double var  = g_stats[256 + k] * invR - mean * mean;
        if (var < 0.0) var = 0.0;
        double a = (double)gamma[k] * rsqrt(var + (double)EPSV);
        g_scale[k] = (float)a;
        g_shift[k] = (float)((double)beta[k] - mean * a);
        g_stats[k] = 0.0;
        g_stats[256 + k] = 0.0;
    }
    // broadcast channels [128,256): analytic from per-batch averages
    float af[Bq];
    {
        double s = 0.0, sq = 0.0;
        for (int b = 0; b < Bq; b++) {
            af[b] = (float)(g_avgms[b * 128 + k] / g_avgms[512 + b]);
            double m = (double)af[b];
            s  += m * (double)Nv;
            sq += m * m * (double)Nv;
        }
        double mean = s * invR;
        double var  = sq * invR - mean * mean;
        if (var < 0.0) var = 0.0;
        double a = (double)gamma[128 + k] * rsqrt(var + (double)EPSV);
        float sck = (float)a;
        float shk = (float)((double)beta[128 + k] - mean * a);
        g_scale[128 + k] = sck;
        g_shift[128 + k] = shk;
        for (int b = 0; b < Bq; b++) xh2[b][k] = fmaf(af[b], sck, shk);
    }
    __syncthreads();   // all avgms reads + xh2 writes done
    // zero avgms
    for (int b = 0; b < Bq; b++) g_avgms[b * 128 + k] = 0.0;
    if (k < Bq) g_avgms[512 + k] = 0.0;
    // bb[b][k] = sum_kk xh2[b][kk] * W[(128+kk)*128 + k]
    float acc[Bq] = {0.f, 0.f, 0.f, 0.f};
    for (int kk = 0; kk < 128; kk++) {
        float w = W[(size_t)(128 + kk) * 128 + k];
#pragma unroll
        for (int b = 0; b < Bq; b++) acc[b] = fmaf(xh2[b][kk], w, acc[b]);
    }
    for (int b = 0; b < Bq; b++) g_bb[b * 128 + k] = acc[b];
}

// ================= SIMT GEMM: 64x128 tile, 256 threads, occ-3 =================
// out[M,128] = (elu(A)*scale+shift)[M,KD] @ W[KD,128] + bias (+ res) (+ bb per batch)
// Thread (ty,tx): rows ty*4..+3, cols {tx*4, tx*4+64}.
template <int KD, bool AVG>
__global__ void __launch_bounds__(256, 3) gemm_kernel(
    const float* __restrict__ A0, const float* __restrict__ A1,
    const float* __restrict__ W, const float* __restrict__ bias,
    const float* __restrict__ res, float* __restrict__ out) {
    __shared__ float As[2][16][64];
    __shared__ float Bs[2][16][128];
    __shared__ float sc[KD], sh[KD];
    const int tid = threadIdx.x;
    const int row0 = blockIdx.x * 64;

    if (tid < KD) { sc[tid] = g_scale[tid]; sh[tid] = g_shift[tid]; }

    const int arow = tid & 63;            // A row within tile
    const int ksg  = (tid >> 6) * 4;      // 0,4,8,12
    const int bkr  = tid >> 4;            // 0..15
    const int bcx  = (tid & 15) * 4;      // 0..60
    const int ty = tid >> 4, tx = tid & 15;
    const int NCH = KD / 16;

    float4 areg, breg[2];

    auto loadAB = [&](int k0) {
        int k = k0 + ksg;
        const float* src;
        if (KD == 256 && k >= 128)
            src = A1 + (size_t)(row0 + arow) * 128 + (k - 128);
        else
            src = A0 + (size_t)(row0 + arow) * 128 + k;
        areg = *(const float4*)src;
#pragma unroll
        for (int q = 0; q < 2; q++)
            breg[q] = *(const float4*)&W[(size_t)(k0 + bkr) * 128 + bcx + q * 64];
    };
    auto storeAB = [&](int buf, int k0) {
        float vv[4] = {areg.x, areg.y, areg.z, areg.w};
#pragma unroll
        for (int j = 0; j < 4; j++) {
            int kl = ksg + j;
            float x = vv[j];
            x = x > 0.f ? x : expm1f(x);
            As[buf][kl][arow] = fmaf(x, sc[k0 + kl], sh[k0 + kl]);
        }
#pragma unroll
        for (int q = 0; q < 2; q++)
            *(float4*)&Bs[buf][bkr][bcx + q * 64] = breg[q];
    };

    float acc[4][8];
#pragma unroll
    for (int i = 0; i < 4; i++)
#pragma unroll
        for (int j = 0; j < 8; j++) acc[i][j] = 0.f;

    loadAB(0);
    __syncthreads();            // sc/sh ready
    storeAB(0, 0);
    __syncthreads();

    for (int ch = 0; ch < NCH; ch++) {
        int nxt = ch + 1;
        if (nxt < NCH) loadAB(nxt * 16);
        int buf = ch & 1;
#pragma unroll
        for (int kk = 0; kk < 16; kk++) {
            float4 a0 = *(const float4*)&As[buf][kk][ty * 4];
            float4 b0 = *(const float4*)&Bs[buf][kk][tx * 4];
            float4 b1 = *(const float4*)&Bs[buf][kk][tx * 4 + 64];
            float av[4] = {a0.x, a0.y, a0.z, a0.w};
            float bv[8] = {b0.x, b0.y, b0.z, b0.w, b1.x, b1.y, b1.z, b1.w};
#pragma unroll
            for (int i = 0; i < 4; i++)
#pragma unroll
                for (int j = 0; j < 8; j++)
                    acc[i][j] = fmaf(av[i], bv[j], acc[i][j]);
        }
        if (nxt < NCH) {
            // store targets the other buffer; post-store sync fences reuse
            storeAB(nxt & 1, nxt * 16);
            __syncthreads();
        }
    }

#pragma unroll
    for (int i = 0; i < 4; i++) {
        int r = row0 + ty * 4 + i;
        int rb = AVG ? (r / Nv) : 0;
#pragma unroll
        for (int jh = 0; jh < 2; jh++) {
            int c = tx * 4 + jh * 64;
            float4 o;
            o.x = acc[i][jh * 4 + 0] + bias[c + 0];
            o.y = acc[i][jh * 4 + 1] + bias[c + 1];
            o.z = acc[i][jh * 4 + 2] + bias[c + 2];
            o.w = acc[i][jh * 4 + 3] + bias[c + 3];
            if (AVG) {
                const float4 bv = *(const float4*)&g_bb[rb * 128 + c];
                o.x += bv.x; o.y += bv.y; o.z += bv.z; o.w += bv.w;
            }
            if (res) {
                const float4 rv = *(const float4*)&res[(size_t)r * 128 + c];
                o.x += rv.x; o.y += rv.y; o.z += rv.z; o.w += rv.w;
            }
            *(float4*)&out[(size_t)r * 128 + c] = o;
        }
    }
}

// ================= avg-block: masked sums + stats ============
#define AVG_RPB 50
__global__ void avg_kernel(const float* __restrict__ x,
                           const float* __restrict__ mask) {
    const int blocksPerBatch = Nv / AVG_RPB;   // 240
    int b = blockIdx.x / blocksPerBatch;
    int n0 = (blockIdx.x % blocksPerBatch) * AVG_RPB;
    int c = threadIdx.x;                       // 128
    float s = 0.f, ms = 0.f, s1 = 0.f, q1 = 0.f;
    for (int i = 0; i < AVG_RPB; i++) {
        int row = b * Nv + n0 + i;
        float mk = mask[row];
        float xe = elu_f(x[(size_t)row * 128 + c]);
        s  += mk * xe;
        s1 += xe;
        q1 += xe * xe;
        if (c == 0) ms += mk;
    }
    atomicAdd(&g_avgms[b * 128 + c], (double)s);
    atomicAdd(&g_stats[c], (double)s1);
    atomicAdd(&g_stats[256 + c], (double)q1);
    if (c == 0) atomicAdd(&g_avgms[512 + b], (double)ms);
}

// ================= final conv =================
__global__ void fstats_kernel(const float* __restrict__ x, int rowsPerBlock) {
    int c = threadIdx.x;                       // 128
    int r0 = blockIdx.x * rowsPerBlock;
    float s = 0.f, sq = 0.f;
    for (int r = r0; r < r0 + rowsPerBlock; r++) {
        float xv = elu_f(x[(size_t)r * 128 + c]);
        s += xv; sq += xv * xv;
    }
    atomicAdd(&g_stats[c], (double)s);
    atomicAdd(&g_stats[256 + c], (double)sq);
}

__global__ void final_kernel(const float* __restrict__ f,
                             const float* __restrict__ W2,
                             const float* __restrict__ b2,
                             float* __restrict__ out) {
    int gwarp = (blockIdx.x * blockDim.x + threadIdx.x) >> 5;
    int lane = threadIdx.x & 31;
    if (gwarp >= RF) return;
    float s = 0.f;
#pragma unroll
    for (int j = 0; j < 4; j++) {
        int k = lane + j * 32;
        float xh = elu_f(f[(size_t)gwarp * 128 + k]) * g_scale[k] + g_shift[k];
        s += xh * W2[k];
    }
#pragma unroll
    for (int off = 16; off; off >>= 1) s += __shfl_down_sync(0xffffffffu, s, off);
    if (lane == 0) out[gwarp] = s + b2[0];
}

// ================= host orchestration =================
extern "C" void kernel_launch(void* const* d_in, const int* in_sizes, int n_in,
                              void* d_out, int out_size) {
    const float* inputs   = (const float*)d_in[0];
    const float* mask     = (const float*)d_in[1];
    const int*   Di_rows  = (const int*)d_in[2];
    const int*   Di_cols  = (const int*)d_in[3];
    const float* Di_vals  = (const float*)d_in[4];
    const int*   DiA_rows = (const int*)d_in[5];
    const int*   DiA_cols = (const int*)d_in[6];
    const float* DiA_vals = (const float*)d_in[7];
    const float* W1       = (const float*)d_in[8];
    const float* b1       = (const float*)d_in[9];
    const float* rn_gamma = (const float*)d_in[10];
    const float* rn_beta  = (const float*)d_in[11];
    const float* rn_W     = (const float*)d_in[12];
    const float* rn_b     = (const float*)d_in[13];
    const float* g2       = (const float*)d_in[14];
    const float* be2      = (const float*)d_in[15];
    const float* W2       = (const float*)d_in[16];
    const float* b2       = (const float*)d_in[17];
    float* out = (float*)d_out;

    float *v, *f, *msg;
    int *cnt, *startA, *startB;
    float2 *edgeA, *edgeB;
    cudaGetSymbolAddress((void**)&v, g_v);
    cudaGetSymbolAddress((void**)&f, g_f);
    cudaGetSymbolAddress((void**)&msg, g_msg);
    cudaGetSymbolAddress((void**)&cnt, g_cnt);
    cudaGetSymbolAddress((void**)&startA, g_startA);
    cudaGetSymbolAddress((void**)&startB, g_startB);
    cudaGetSymbolAddress((void**)&edgeA, g_edgeA);
    cudaGetSymbolAddress((void**)&edgeB, g_edgeB);

    auto build_csr = [&](const int* rows, const int* cols, const float* vals,
                         int* start, float2* edges) {
        cudaMemsetAsync(cnt, 0, BINS * sizeof(int), 0);
        hist_kernel<<<NNZ / 256, 256>>>(rows);
        scan_block_kernel<<<96, 1024>>>();
        scan_top_kernel<<<1, 32>>>();
        scan_finish_kernel<<<96, 1024>>>(start);
        fill_kernel<<<NNZ / 256, 256>>>(rows, cols, vals, edges);
    };

    // CSR for both sparse operators
    build_csr(DiA_rows, DiA_cols, DiA_vals, startA, edgeA);
    build_csr(Di_rows, Di_cols, Di_vals, startB, edgeB);

    // conv1 + init f = 0
    conv1_kernel<<<(RV * C) / 256, 256>>>(inputs, W1, b1);
    cudaMemsetAsync(f, 0, (size_t)RF * C * sizeof(float), 0);

    for (int i = 0; i < 16; i++) {
        const float* W0  = rn_W + (size_t)i * 2 * 256 * 128;
        const float* Wb0 = rn_b + (size_t)i * 2 * 128;
        const float* gm0 = rn_gamma + (size_t)i * 2 * 256;
        const float* bt0 = rn_beta + (size_t)i * 2 * 256;

        if ((i & 1) == 0) {
            // ---- dir block ----
            spmm_kernel<<<RV / 4, 128>>>(startA, edgeA, f, FN * C, msg, Nv * C);
            stats2_kernel<<<RV / EC_ROWS, 128>>>(v, msg);
            prep_kernel<<<1, 256>>>(gm0, bt0, 256, 1.0 / RV);
            gemm_kernel<256, false><<<RV / 64, 256>>>(v, msg, W0, Wb0, v, v);

            spmm_kernel<<<RF / 4, 128>>>(startB, edgeB, v, Nv * C, msg, FN * C);
            stats2_kernel<<<RF / EC_ROWS, 128>>>(f, msg);
            prep_kernel<<<1, 256>>>(gm0 + 256, bt0 + 256, 256, 1.0 / RF);
            gemm_kernel<256, false><<<RF / 64, 256>>>(f, msg, W0 + 256 * 128,
                                                      Wb0 + 128, nullptr, f);
        } else {
            // ---- avg block ----
            avg_kernel<<<Bq * (Nv / AVG_RPB), 128>>>(v, mask);
            prep_avg_kernel<<<1, 128>>>(gm0, bt0, W0);
            gemm_kernel<128, true><<<RV / 64, 256>>>(v, nullptr, W0, Wb0,
                                                     nullptr, msg);

            avg_kernel<<<Bq * (Nv / AVG_RPB), 128>>>(msg, mask);
            prep_avg_kernel<<<1, 128>>>(gm0 + 256, bt0 + 256, W0 + 256 * 128);
            gemm_kernel<128, true><<<RV / 64, 256>>>(msg, nullptr,
                                                     W0 + 256 * 128, Wb0 + 128,
                                                     v, v);
        }
    }

    // final conv
    fstats_kernel<<<RF / 128, 128>>>(f, 128);
    prep_kernel<<<1, 128>>>(g2, be2, 128, 1.0 / RF);
    final_kernel<<<(RF + 7) / 8, 256>>>(f, W2, b2, out);
}

// round 9
// speedup vs baseline: 1.6043x; 1.0083x over previous
#include <cuda_runtime.h>
#include <math.h>
#include <stdint.h>

#define Bq 4
#define Nv 12000
#define FN 24000
#define C 128
#define NNZ (48 * FN)     // 1,152,000
#define EPSV 1e-5f

#define RV (Bq * Nv)      // 48000 vertex rows
#define RF (Bq * FN)      // 96000 face rows

#define BINS 98304        // 96 * 1024 (covers 96000 rows)
#define EC_ROWS 64

// ---------------- scratch (device globals: allocation-free) ----------------
__device__ float  g_v[RV * C];
__device__ float  g_f[RF * C];
__device__ float  g_msg[RF * C];
__device__ double g_statsL[33 * 512];    // per-conv: sum[0,256), sumsq[256,512)
__device__ double g_avgmsL[16 * 520];    // per-avg-conv: avgsum[0,512), masksum[512,516)

// CSR build scratch
__device__ int    g_cnt[BINS];
__device__ int    g_incl[BINS];
__device__ int    g_bsum[96];
__device__ int    g_cursor[BINS];
__device__ int    g_startA[BINS + 1];   // DiA: 48000 rows
__device__ int    g_startB[BINS + 1];   // Di : 96000 rows
__device__ float2 g_edgeA[NNZ];         // (val, bitcast col), row-sorted
__device__ float2 g_edgeB[NNZ];

__device__ __forceinline__ float elu_f(float x) {
    return x > 0.f ? x : expm1f(x);
}

// ================= CSR build =================
__global__ void hist_kernel(const int* __restrict__ rows) {
    int i = blockIdx.x * blockDim.x + threadIdx.x;
    if (i < NNZ) atomicAdd(&g_cnt[rows[i]], 1);
}

__global__ void scan_block_kernel() {
    __shared__ int sd[1024];
    int t = threadIdx.x;
    int gid = blockIdx.x * 1024 + t;
    sd[t] = g_cnt[gid];
    __syncthreads();
    for (int off = 1; off < 1024; off <<= 1) {
        int add = (t >= off) ? sd[t - off] : 0;
        __syncthreads();
        sd[t] += add;
        __syncthreads();
    }
    g_incl[gid] = sd[t];
    if (t == 1023) g_bsum[blockIdx.x] = sd[1023];
}

__global__ void scan_top_kernel() {
    if (threadIdx.x == 0) {
        int run = 0;
        for (int b = 0; b < 96; b++) { int tt = g_bsum[b]; g_bsum[b] = run; run += tt; }
    }
}

__global__ void scan_finish_kernel(int* __restrict__ start) {
    int t = threadIdx.x;
    int gid = blockIdx.x * 1024 + t;
    int excl = g_incl[gid] - g_cnt[gid] + g_bsum[blockIdx.x];
    start[gid] = excl;
    g_cursor[gid] = excl;
    if (gid == BINS - 1) start[BINS] = excl + g_cnt[gid];
}

__global__ void fill_kernel(const int* __restrict__ rows,
                            const int* __restrict__ cols,
                            const float* __restrict__ vals,
                            float2* __restrict__ edges) {
    int i = blockIdx.x * blockDim.x + threadIdx.x;
    if (i >= NNZ) return;
    int pos = atomicAdd(&g_cursor[rows[i]], 1);
    edges[pos] = make_float2(vals[i], __int_as_float(cols[i]));
}

// ================= SpMM (CSR, atomic-free) =================
__global__ void spmm_kernel(const int* __restrict__ start,
                            const float2* __restrict__ edges,
                            const float* __restrict__ in, int inStride,
                            float* __restrict__ out, int outStride) {
    int t = threadIdx.x;
    int r = blockIdx.x * 4 + (t >> 5);
    int lane = t & 31;
    int b = lane >> 3, k4 = lane & 7;
    int s = start[r], e = start[r + 1];
    float4 acc = make_float4(0.f, 0.f, 0.f, 0.f);
    const float* inb = in + (size_t)b * inStride;
    for (int i = s; i < e; i++) {
        float2 ed = edges[i];
        int c = __float_as_int(ed.y);
        float4 q = *(const float4*)&inb[c * 32 + k4 * 4];
        acc.x = fmaf(ed.x, q.x, acc.x);
        acc.y = fmaf(ed.x, q.y, acc.y);
        acc.z = fmaf(ed.x, q.z, acc.z);
        acc.w = fmaf(ed.x, q.w, acc.w);
    }
    *(float4*)&out[(size_t)b * outStride + r * 32 + k4 * 4] = acc;
}

// ================= conv1 =================
__global__ void conv1_kernel(const float* __restrict__ in,
                             const float* __restrict__ W1,
                             const float* __restrict__ b1) {
    int idx = blockIdx.x * blockDim.x + threadIdx.x;
    if (idx >= RV * C) return;
    int r = idx >> 7, c = idx & 127;
    float x0 = in[r * 3 + 0], x1 = in[r * 3 + 1], x2 = in[r * 3 + 2];
    g_v[idx] = x0 * W1[c] + x1 * W1[128 + c] + x2 * W1[256 + c] + b1[c];
}

// ================= stats over elu of two sources (dir blocks) =================
__global__ void stats2_kernel(const float* __restrict__ x0,
                              const float* __restrict__ x1,
                              double* __restrict__ st) {
    int c = threadIdx.x;                      // 128
    int r0 = blockIdx.x * EC_ROWS;
    float s1 = 0.f, q1 = 0.f, s2 = 0.f, q2 = 0.f;
    for (int i = 0; i < EC_ROWS; i++) {
        int row = r0 + i;
        float xa = elu_f(x0[(size_t)row * 128 + c]);
        float xm = elu_f(x1[(size_t)row * 128 + c]);
        s1 += xa; q1 += xa * xa;
        s2 += xm; q2 += xm * xm;
    }
    atomicAdd(&st[c], (double)s1);
    atomicAdd(&st[256 + c], (double)q1);
    atomicAdd(&st[128 + c], (double)s2);
    atomicAdd(&st[384 + c], (double)q2);
}

// ================= SIMT GEMM: 64x128 tile, 256 threads, occ-3 =================
// out[M,128] = (elu(A)*scale+shift)[M,KD] @ W[KD,128] + bias (+ res) (+ bb per batch)
// scale/shift computed in-prologue from per-conv stats slot (+ analytic bcast & bb
// fold for AVG). Thread (ty,tx): rows ty*4..+3, cols {tx*4, tx*4+64}.
template <int KD, bool AVG>
__global__ void __launch_bounds__(256, 3) gemm_kernel(
    const float* __restrict__ A0, const float* __restrict__ A1,
    const float* __restrict__ W, const float* __restrict__ bias,
    const float* __restrict__ res, float* __restrict__ out,
    const double* __restrict__ stats,
    const float* __restrict__ gamma, const float* __restrict__ beta,
    double invR, const double* __restrict__ avgms) {
    __shared__ float As[2][16][64];
    __shared__ float Bs[2][16][128];
    __shared__ float sc[KD], sh[KD];
    __shared__ float xh2s[AVG ? 4 : 1][AVG ? 128 : 1];
    __shared__ float bbp[AVG ? 2 : 1][AVG ? 4 : 1][AVG ? 128 : 1];
    __shared__ float bbs[AVG ? 4 : 1][AVG ? 128 : 1];
    const int tid = threadIdx.x;
    const int row0 = blockIdx.x * 64;

    // ---- prologue: BN scale/shift from stats slot ----
    if (tid < KD) {
        double mean = stats[tid] * invR;
        double var  = stats[256 + tid] * invR - mean * mean;
        if (var < 0.0) var = 0.0;
        double a = (double)gamma[tid] * rsqrt(var + (double)EPSV);
        sc[tid] = (float)a;
        sh[tid] = (float)((double)beta[tid] - mean * a);
    }
    if (AVG && tid < 128) {
        // broadcast channels [128,256): analytic stats from per-batch averages
        float af[Bq];
        double s = 0.0, sq = 0.0;
        for (int b = 0; b < Bq; b++) {
            af[b] = (float)(avgms[b * 128 + tid] / avgms[512 + b]);
            double m = (double)af[b];
            s  += m * (double)Nv;
            sq += m * m * (double)Nv;
        }
        double mean = s * (1.0 / (double)RV);
        double var  = sq * (1.0 / (double)RV) - mean * mean;
        if (var < 0.0) var = 0.0;
        double a = (double)gamma[128 + tid] * rsqrt(var + (double)EPSV);
        float sck = (float)a;
        float shk = (float)((double)beta[128 + tid] - mean * a);
#pragma unroll
        for (int b = 0; b < Bq; b++) xh2s[b][tid] = fmaf(af[b], sck, shk);
    }

    const int arow = tid & 63;            // A row within tile
    const int ksg  = (tid >> 6) * 4;      // 0,4,8,12
    const int bkr  = tid >> 4;            // 0..15
    const int bcx  = (tid & 15) * 4;      // 0..60
    const int ty = tid >> 4, tx = tid & 15;
    const int NCH = KD / 16;

    float4 areg, breg[2];

    auto loadAB = [&](int k0) {
        int k = k0 + ksg;
        const float* src;
        if (KD == 256 && k >= 128)
            src = A1 + (size_t)(row0 + arow) * 128 + (k - 128);
        else
            src = A0 + (size_t)(row0 + arow) * 128 + k;
        areg = *(const float4*)src;
#pragma unroll
        for (int q = 0; q < 2; q++)
            breg[q] = *(const float4*)&W[(size_t)(k0 + bkr) * 128 + bcx + q * 64];
    };
    auto storeAB = [&](int buf, int k0) {
        float vv[4] = {areg.x, areg.y, areg.z, areg.w};
#pragma unroll
        for (int j = 0; j < 4; j++) {
            int kl = ksg + j;
            float x = vv[j];
            x = x > 0.f ? x : expm1f(x);
            As[buf][kl][arow] = fmaf(x, sc[k0 + kl], sh[k0 + kl]);
        }
#pragma unroll
        for (int q = 0; q < 2; q++)
            *(float4*)&Bs[buf][bkr][bcx + q * 64] = breg[q];
    };

    float acc[4][8];
#pragma unroll
    for (int i = 0; i < 4; i++)
#pragma unroll
        for (int j = 0; j < 8; j++) acc[i][j] = 0.f;

    loadAB(0);
    __syncthreads();            // sc/sh (+xh2s) ready

    if (AVG) {
        // bb fold: bb[b][c] = sum_kk xh2[b][kk] * W[(128+kk)*128 + c]
        int c = tid & 127, h = tid >> 7;
        float p0 = 0.f, p1 = 0.f, p2 = 0.f, p3 = 0.f;
        for (int kk = h * 64; kk < h * 64 + 64; kk++) {
            float w = W[(size_t)(128 + kk) * 128 + c];
            p0 = fmaf(xh2s[0][kk], w, p0);
            p1 = fmaf(xh2s[1][kk], w, p1);
            p2 = fmaf(xh2s[2][kk], w, p2);
            p3 = fmaf(xh2s[3][kk], w, p3);
        }
        bbp[h][0][c] = p0; bbp[h][1][c] = p1;
        bbp[h][2][c] = p2; bbp[h][3][c] = p3;
        __syncthreads();
        if (tid < 128) {
#pragma unroll
            for (int b = 0; b < Bq; b++)
                bbs[b][tid] = bbp[0][b][tid] + bbp[1][b][tid];
        }
    }

    storeAB(0, 0);
    __syncthreads();

    for (int ch = 0; ch < NCH; ch++) {
        int nxt = ch + 1;
        if (nxt < NCH) loadAB(nxt * 16);
        int buf = ch & 1;
#pragma unroll
        for (int kk = 0; kk < 16; kk++) {
            float4 a0 = *(const float4*)&As[buf][kk][ty * 4];
            float4 b0 = *(const float4*)&Bs[buf][kk][tx * 4];
            float4 b1 = *(const float4*)&Bs[buf][kk][tx * 4 + 64];
            float av[4] = {a0.x, a0.y, a0.z, a0.w};
            float bv[8] = {b0.x, b0.y, b0.z, b0.w, b1.x, b1.y, b1.z, b1.w};
#pragma unroll
            for (int i = 0; i < 4; i++)
#pragma unroll
                for (int j = 0; j < 8; j++)
                    acc[i][j] = fmaf(av[i], bv[j], acc[i][j]);
        }
        if (nxt < NCH) {
            storeAB(nxt & 1, nxt * 16);
            __syncthreads();
        }
    }

#pragma unroll
    for (int i = 0; i < 4; i++) {
        int r = row0 + ty * 4 + i;
        int rb = AVG ? (r / Nv) : 0;
#pragma unroll
        for (int jh = 0; jh < 2; jh++) {
            int c = tx * 4 + jh * 64;
            float4 o;
            o.x = acc[i][jh * 4 + 0] + bias[c + 0];
            o.y = acc[i][jh * 4 + 1] + bias[c + 1];
            o.z = acc[i][jh * 4 + 2] + bias[c + 2];
            o.w = acc[i][jh * 4 + 3] + bias[c + 3];
            if (AVG) {
                o.x += bbs[rb][c + 0];
                o.y += bbs[rb][c + 1];
                o.z += bbs[rb][c + 2];
                o.w += bbs[rb][c + 3];
            }
            if (res) {
                const float4 rv = *(const float4*)&res[(size_t)r * 128 + c];
                o.x += rv.x; o.y += rv.y; o.z += rv.z; o.w += rv.w;
            }
            *(float4*)&out[(size_t)r * 128 + c] = o;
        }
    }
}

// ================= avg-block: masked sums + stats ============
#define AVG_RPB 50
__global__ void avg_kernel(const float* __restrict__ x,
                           const float* __restrict__ mask,
                           double* __restrict__ st,
                           double* __restrict__ am) {
    const int blocksPerBatch = Nv / AVG_RPB;   // 240
    int b = blockIdx.x / blocksPerBatch;
    int n0 = (blockIdx.x % blocksPerBatch) * AVG_RPB;
    int c = threadIdx.x;                       // 128
    float s = 0.f, ms = 0.f, s1 = 0.f, q1 = 0.f;
    for (int i = 0; i < AVG_RPB; i++) {
        int row = b * Nv + n0 + i;
        float mk = mask[row];
        float xe = elu_f(x[(size_t)row * 128 + c]);
        s  += mk * xe;
        s1 += xe;
        q1 += xe * xe;
        if (c == 0) ms += mk;
    }
    atomicAdd(&am[b * 128 + c], (double)s);
    atomicAdd(&st[c], (double)s1);
    atomicAdd(&st[256 + c], (double)q1);
    if (c == 0) atomicAdd(&am[512 + b], (double)ms);
}

// ================= final conv =================
__global__ void fstats_kernel(const float* __restrict__ x,
                              double* __restrict__ st, int rowsPerBlock) {
    int c = threadIdx.x;                       // 128
    int r0 = blockIdx.x * rowsPerBlock;
    float s = 0.f, sq = 0.f;
    for (int r = r0; r < r0 + rowsPerBlock; r++) {
        float xv = elu_f(x[(size_t)r * 128 + c]);
        s += xv; sq += xv * xv;
    }
    atomicAdd(&st[c], (double)s);
    atomicAdd(&st[256 + c], (double)sq);
}

__global__ void final_kernel(const float* __restrict__ f,
                             const float* __restrict__ W2,
                             const float* __restrict__ b2,
                             float* __restrict__ out,
                             const double* __restrict__ stats,
                             const float* __restrict__ g2,
                             const float* __restrict__ be2) {
    __shared__ float sc[128], sh[128];
    int tid = threadIdx.x;
    if (tid < 128) {
        const double invR = 1.0 / (double)RF;
        double mean = stats[tid] * invR;
        double var  = stats[256 + tid] * invR - mean * mean;
        if (var < 0.0) var = 0.0;
        double a = (double)g2[tid] * rsqrt(var + (double)EPSV);
        sc[tid] = (float)a;
        sh[tid] = (float)((double)be2[tid] - mean * a);
    }
    __syncthreads();
    int gwarp = blockIdx.x * 8 + (tid >> 5);
    int lane = tid & 31;
    if (gwarp >= RF) return;
    float s = 0.f;
#pragma unroll
    for (int j = 0; j < 4; j++) {
        int k = lane + j * 32;
        float xh = fmaf(elu_f(f[(size_t)gwarp * 128 + k]), sc[k], sh[k]);
        s += xh * W2[k];
    }
#pragma unroll
    for (int off = 16; off; off >>= 1) s += __shfl_down_sync(0xffffffffu, s, off);
    if (lane == 0) out[gwarp] = s + b2[0];
}

// ================= host orchestration =================
extern "C" void kernel_launch(void* const* d_in, const int* in_sizes, int n_in,
                              void* d_out, int out_size) {
    const float* inputs   = (const float*)d_in[0];
    const float* mask     = (const float*)d_in[1];
    const int*   Di_rows  = (const int*)d_in[2];
    const int*   Di_cols  = (const int*)d_in[3];
    const float* Di_vals  = (const float*)d_in[4];
    const int*   DiA_rows = (const int*)d_in[5];
    const int*   DiA_cols = (const int*)d_in[6];
    const float* DiA_vals = (const float*)d_in[7];
    const float* W1       = (const float*)d_in[8];
    const float* b1       = (const float*)d_in[9];
    const float* rn_gamma = (const float*)d_in[10];
    const float* rn_beta  = (const float*)d_in[11];
    const float* rn_W     = (const float*)d_in[12];
    const float* rn_b     = (const float*)d_in[13];
    const float* g2       = (const float*)d_in[14];
    const float* be2      = (const float*)d_in[15];
    const float* W2       = (const float*)d_in[16];
    const float* b2       = (const float*)d_in[17];
    float* out = (float*)d_out;

    float *v, *f, *msg;
    double *statsL, *avgmsL;
    int *cnt, *startA, *startB;
    float2 *edgeA, *edgeB;
    cudaGetSymbolAddress((void**)&v, g_v);
    cudaGetSymbolAddress((void**)&f, g_f);
    cudaGetSymbolAddress((void**)&msg, g_msg);
    cudaGetSymbolAddress((void**)&statsL, g_statsL);
    cudaGetSymbolAddress((void**)&avgmsL, g_avgmsL);
    cudaGetSymbolAddress((void**)&cnt, g_cnt);
    cudaGetSymbolAddress((void**)&startA, g_startA);
    cudaGetSymbolAddress((void**)&startB, g_startB);
    cudaGetSymbolAddress((void**)&edgeA, g_edgeA);
    cudaGetSymbolAddress((void**)&edgeB, g_edgeB);

    auto build_csr = [&](const int* rows, const int* cols, const float* vals,
                         int* start, float2* edges) {
        cudaMemsetAsync(cnt, 0, BINS * sizeof(int), 0);
        hist_kernel<<<NNZ / 256, 256>>>(rows);
        scan_block_kernel<<<96, 1024>>>();
        scan_top_kernel<<<1, 32>>>();
        scan_finish_kernel<<<96, 1024>>>(start);
        fill_kernel<<<NNZ / 256, 256>>>(rows, cols, vals, edges);
    };

    // zero all stats slots once per replay
    cudaMemsetAsync(statsL, 0, 33 * 512 * sizeof(double), 0);
    cudaMemsetAsync(avgmsL, 0, 16 * 520 * sizeof(double), 0);

    // CSR for both sparse operators
    build_csr(DiA_rows, DiA_cols, DiA_vals, startA, edgeA);
    build_csr(Di_rows, Di_cols, Di_vals, startB, edgeB);

    // conv1 + init f = 0
    conv1_kernel<<<(RV * C) / 256, 256>>>(inputs, W1, b1);
    cudaMemsetAsync(f, 0, (size_t)RF * C * sizeof(float), 0);

    for (int i = 0; i < 16; i++) {
        const float* W0  = rn_W + (size_t)i * 2 * 256 * 128;
        const float* Wb0 = rn_b + (size_t)i * 2 * 128;
        const float* gm0 = rn_gamma + (size_t)i * 2 * 256;
        const float* bt0 = rn_beta + (size_t)i * 2 * 256;
        double* st0 = statsL + (size_t)(2 * i) * 512;
        double* st1 = statsL + (size_t)(2 * i + 1) * 512;

        if ((i & 1) == 0) {
            // ---- dir block ----
            if (i == 0)
                cudaMemsetAsync(msg, 0, (size_t)RV * C * sizeof(float), 0);  // f==0
            else
                spmm_kernel<<<RV / 4, 128>>>(startA, edgeA, f, FN * C, msg, Nv * C);
            stats2_kernel<<<RV / EC_ROWS, 128>>>(v, msg, st0);
            gemm_kernel<256, false><<<RV / 64, 256>>>(v, msg, W0, Wb0, v, v,
                                                      st0, gm0, bt0, 1.0 / RV,
                                                      nullptr);

            spmm_kernel<<<RF / 4, 128>>>(startB, edgeB, v, Nv * C, msg, FN * C);
            stats2_kernel<<<RF / EC_ROWS, 128>>>(f, msg, st1);
            gemm_kernel<256, false><<<RF / 64, 256>>>(f, msg, W0 + 256 * 128,
                                                      Wb0 + 128, nullptr, f,
                                                      st1, gm0 + 256, bt0 + 256,
                                                      1.0 / RF, nullptr);
        } else {
            // ---- avg block ----
            double* am0 = avgmsL + (size_t)((i >> 1) * 2) * 520;
            double* am1 = avgmsL + (size_t)((i >> 1) * 2 + 1) * 520;

            avg_kernel<<<Bq * (Nv / AVG_RPB), 128>>>(v, mask, st0, am0);
            gemm_kernel<128, true><<<RV / 64, 256>>>(v, nullptr, W0, Wb0,
                                                     nullptr, msg,
                                                     st0, gm0, bt0, 1.0 / RV,
                                                     am0);

            avg_kernel<<<Bq * (Nv / AVG_RPB), 128>>>(msg, mask, st1, am1);
            gemm_kernel<128, true><<<RV / 64, 256>>>(msg, nullptr,
                                                     W0 + 256 * 128, Wb0 + 128,
                                                     v, v,
                                                     st1, gm0 + 256, bt0 + 256,
                                                     1.0 / RV, am1);
        }
    }

    // final conv
    double* stF = statsL + (size_t)32 * 512;
    fstats_kernel<<<RF / 128, 128>>>(f, stF, 128);
    final_kernel<<<RF / 8, 256>>>(f, W2, b2, out, stF, g2, be2);
}

// round 10
// speedup vs baseline: 1.6455x; 1.0257x over previous
#include <cuda_runtime.h>
#include <math.h>
#include <stdint.h>

#define Bq 4
#define Nv 12000
#define FN 24000
#define C 128
#define NNZ (48 * FN)     // 1,152,000
#define EPSV 1e-5f

#define RV (Bq * Nv)      // 48000 vertex rows
#define RF (Bq * FN)      // 96000 face rows

#define BINS 98304        // 96 * 1024 (covers 96000 rows)

// ---------------- scratch (device globals: allocation-free) ----------------
__device__ float  g_v[RV * C];
__device__ float  g_f[RF * C];
__device__ float  g_msg[RF * C];
__device__ double g_statsL[33 * 512];   // per-conv: sum[0,256), sumsq[256,512)
__device__ double g_avgmsL[16 * 512];   // per-avg-conv: masked avgsum [B][128]
__device__ double g_msum[Bq];           // per-batch mask sums

// CSR build scratch
__device__ int    g_cnt[BINS];
__device__ int    g_incl[BINS];
__device__ int    g_bsum[96];
__device__ int    g_cursor[BINS];
__device__ int    g_startA[BINS + 1];   // DiA: 48000 rows
__device__ int    g_startB[BINS + 1];   // Di : 96000 rows
__device__ float2 g_edgeA[NNZ];         // (val, bitcast col), row-sorted
__device__ float2 g_edgeB[NNZ];

__device__ __forceinline__ float elu_f(float x) {
    return x > 0.f ? x : expm1f(x);
}

// ================= CSR build =================
__global__ void hist_kernel(const int* __restrict__ rows) {
    int i = blockIdx.x * blockDim.x + threadIdx.x;
    if (i < NNZ) atomicAdd(&g_cnt[rows[i]], 1);
}

__global__ void scan_block_kernel() {
    __shared__ int sd[1024];
    int t = threadIdx.x;
    int gid = blockIdx.x * 1024 + t;
    sd[t] = g_cnt[gid];
    __syncthreads();
    for (int off = 1; off < 1024; off <<= 1) {
        int add = (t >= off) ? sd[t - off] : 0;
        __syncthreads();
        sd[t] += add;
        __syncthreads();
    }
    g_incl[gid] = sd[t];
    if (t == 1023) g_bsum[blockIdx.x] = sd[1023];
}

__global__ void scan_top_kernel() {
    if (threadIdx.x == 0) {
        int run = 0;
        for (int b = 0; b < 96; b++) { int tt = g_bsum[b]; g_bsum[b] = run; run += tt; }
    }
}

__global__ void scan_finish_kernel(int* __restrict__ start) {
    int t = threadIdx.x;
    int gid = blockIdx.x * 1024 + t;
    int excl = g_incl[gid] - g_cnt[gid] + g_bsum[blockIdx.x];
    start[gid] = excl;
    g_cursor[gid] = excl;
    if (gid == BINS - 1) start[BINS] = excl + g_cnt[gid];
}

__global__ void fill_kernel(const int* __restrict__ rows,
                            const int* __restrict__ cols,
                            const float* __restrict__ vals,
                            float2* __restrict__ edges) {
    int i = blockIdx.x * blockDim.x + threadIdx.x;
    if (i >= NNZ) return;
    int pos = atomicAdd(&g_cursor[rows[i]], 1);
    edges[pos] = make_float2(vals[i], __int_as_float(cols[i]));
}

// ================= SpMM (CSR, atomic-free) =================
__global__ void spmm_kernel(const int* __restrict__ start,
                            const float2* __restrict__ edges,
                            const float* __restrict__ in, int inStride,
                            float* __restrict__ out, int outStride) {
    int t = threadIdx.x;
    int r = blockIdx.x * 4 + (t >> 5);
    int lane = t & 31;
    int b = lane >> 3, k4 = lane & 7;
    int s = start[r], e = start[r + 1];
    float4 acc = make_float4(0.f, 0.f, 0.f, 0.f);
    const float* inb = in + (size_t)b * inStride;
    for (int i = s; i < e; i++) {
        float2 ed = edges[i];
        int c = __float_as_int(ed.y);
        float4 q = *(const float4*)&inb[c * 32 + k4 * 4];
        acc.x = fmaf(ed.x, q.x, acc.x);
        acc.y = fmaf(ed.x, q.y, acc.y);
        acc.z = fmaf(ed.x, q.z, acc.z);
        acc.w = fmaf(ed.x, q.w, acc.w);
    }
    *(float4*)&out[(size_t)b * outStride + r * 32 + k4 * 4] = acc;
}

// ================= conv1 (fused stats -> slot0 first half) =================
__global__ void conv1_kernel(const float* __restrict__ in,
                             const float* __restrict__ W1,
                             const float* __restrict__ b1,
                             double* __restrict__ st) {
    int c = threadIdx.x;                  // 128
    int r0 = blockIdx.x * 64;
    float w0 = W1[c], w1 = W1[128 + c], w2 = W1[256 + c], bb = b1[c];
    float s = 0.f, q = 0.f;
    for (int i = 0; i < 64; i++) {
        int r = r0 + i;
        float x0 = in[r * 3 + 0], x1 = in[r * 3 + 1], x2 = in[r * 3 + 2];
        float val = fmaf(x0, w0, fmaf(x1, w1, fmaf(x2, w2, bb)));
        g_v[(size_t)r * 128 + c] = val;
        float e = elu_f(val);
        s += e; q += e * e;
    }
    atomicAdd(&st[c], (double)s);
    atomicAdd(&st[256 + c], (double)q);
}

// ================= slim stats over msg (second-half channels) =================
__global__ void statsm_kernel(const float* __restrict__ x,
                              double* __restrict__ st) {
    int c = threadIdx.x;                  // 128
    int r0 = blockIdx.x * 64;
    float s = 0.f, q = 0.f;
    for (int i = 0; i < 64; i++) {
        float e = elu_f(x[(size_t)(r0 + i) * 128 + c]);
        s += e; q += e * e;
    }
    atomicAdd(&st[128 + c], (double)s);
    atomicAdd(&st[384 + c], (double)q);
}

// ================= per-batch mask sums (once per replay) =================
__global__ void masksum_kernel(const float* __restrict__ mask) {
    __shared__ float sd[256];
    int b = blockIdx.x, t = threadIdx.x;
    float s = 0.f;
    for (int i = t; i < Nv; i += 256) s += mask[b * Nv + i];
    sd[t] = s;
    __syncthreads();
    for (int off = 128; off; off >>= 1) {
        if (t < off) sd[t] += sd[t + off];
        __syncthreads();
    }
    if (t == 0) g_msum[b] = (double)sd[0];
}

// ================= SIMT GEMM: 64x128 tile, 256 threads, occ-3 =================
// out[M,128] = (elu(A)*scale+shift)[M,KD] @ W[KD,128] + bias (+ res) (+ bb)
// Prologue: BN scale/shift from stats slot (+ analytic bcast & bb fold for AVG).
// Epilogue: optional fused elu-stats (+ masked avgsum) of the OUTPUT into
// the consumer's slot.
template <int KD, bool AVG, bool MSUM>
__global__ void __launch_bounds__(256, 3) gemm_kernel(
    const float* __restrict__ A0, const float* __restrict__ A1,
    const float* __restrict__ W, const float* __restrict__ bias,
    const float* __restrict__ res, float* __restrict__ out,
    const double* __restrict__ stats,
    const float* __restrict__ gamma, const float* __restrict__ beta,
    double invR, const double* __restrict__ avgms,
    double* __restrict__ statsOut, double* __restrict__ amOut,
    const float* __restrict__ mask) {
    __shared__ float As[2][16][64];
    __shared__ float Bs[2][16][128];
    __shared__ float sc[KD], sh[KD];
    __shared__ float xh2s[AVG ? 4 : 1][AVG ? 128 : 1];
    __shared__ float bbp[AVG ? 2 : 1][AVG ? 4 : 1][AVG ? 128 : 1];
    __shared__ float bbs[AVG ? 4 : 1][AVG ? 128 : 1];
    __shared__ int rbarr[16];
    const int tid = threadIdx.x;
    const int row0 = blockIdx.x * 64;

    // ---- prologue: BN scale/shift from stats slot ----
    if (tid < KD) {
        double mean = stats[tid] * invR;
        double var  = stats[256 + tid] * invR - mean * mean;
        if (var < 0.0) var = 0.0;
        double a = (double)gamma[tid] * rsqrt(var + (double)EPSV);
        sc[tid] = (float)a;
        sh[tid] = (float)((double)beta[tid] - mean * a);
    }
    if (AVG && tid < 128) {
        float af[Bq];
        double s = 0.0, sq = 0.0;
        for (int b = 0; b < Bq; b++) {
            af[b] = (float)(avgms[b * 128 + tid] / g_msum[b]);
            double m = (double)af[b];
            s  += m * (double)Nv;
            sq += m * m * (double)Nv;
        }
        double mean = s * (1.0 / (double)RV);
        double var  = sq * (1.0 / (double)RV) - mean * mean;
        if (var < 0.0) var = 0.0;
        double a = (double)gamma[128 + tid] * rsqrt(var + (double)EPSV);
        float sck = (float)a;
        float shk = (float)((double)beta[128 + tid] - mean * a);
#pragma unroll
        for (int b = 0; b < Bq; b++) xh2s[b][tid] = fmaf(af[b], sck, shk);
    }

    const int arow = tid & 63;
    const int ksg  = (tid >> 6) * 4;
    const int bkr  = tid >> 4;
    const int bcx  = (tid & 15) * 4;
    const int ty = tid >> 4, tx = tid & 15;
    const int NCH = KD / 16;

    float4 areg, breg[2];

    auto loadAB = [&](int k0) {
        int k = k0 + ksg;
        const float* src;
        if (KD == 256 && k >= 128)
            src = A1 + (size_t)(row0 + arow) * 128 + (k - 128);
        else
            src = A0 + (size_t)(row0 + arow) * 128 + k;
        areg = *(const float4*)src;
#pragma unroll
        for (int q = 0; q < 2; q++)
            breg[q] = *(const float4*)&W[(size_t)(k0 + bkr) * 128 + bcx + q * 64];
    };
    auto storeAB = [&](int buf, int k0) {
        float vv[4] = {areg.x, areg.y, areg.z, areg.w};
#pragma unroll
        for (int j = 0; j < 4; j++) {
            int kl = ksg + j;
            float x = vv[j];
            x = x > 0.f ? x : expm1f(x);
            As[buf][kl][arow] = fmaf(x, sc[k0 + kl], sh[k0 + kl]);
        }
#pragma unroll
        for (int q = 0; q < 2; q++)
            *(float4*)&Bs[buf][bkr][bcx + q * 64] = breg[q];
    };

    float acc[4][8];
#pragma unroll
    for (int i = 0; i < 4; i++)
#pragma unroll
        for (int j = 0; j < 8; j++) acc[i][j] = 0.f;

    loadAB(0);
    __syncthreads();            // sc/sh (+xh2s) ready

    if (AVG) {
        // bb fold: bb[b][c] = sum_kk xh2[b][kk] * W[(128+kk)*128 + c]
        int c = tid & 127, h = tid >> 7;
        float p0 = 0.f, p1 = 0.f, p2 = 0.f, p3 = 0.f;
        for (int kk = h * 64; kk < h * 64 + 64; kk++) {
            float w = W[(size_t)(128 + kk) * 128 + c];
            p0 = fmaf(xh2s[0][kk], w, p0);
            p1 = fmaf(xh2s[1][kk], w, p1);
            p2 = fmaf(xh2s[2][kk], w, p2);
            p3 = fmaf(xh2s[3][kk], w, p3);
        }
        bbp[h][0][c] = p0; bbp[h][1][c] = p1;
        bbp[h][2][c] = p2; bbp[h][3][c] = p3;
        __syncthreads();
        if (tid < 128) {
#pragma unroll
            for (int b = 0; b < Bq; b++)
                bbs[b][tid] = bbp[0][b][tid] + bbp[1][b][tid];
        }
    }

    storeAB(0, 0);
    __syncthreads();

    for (int ch = 0; ch < NCH; ch++) {
        int nxt = ch + 1;
        if (nxt < NCH) loadAB(nxt * 16);
        int buf = ch & 1;
#pragma unroll
        for (int kk = 0; kk < 16; kk++) {
            float4 a0 = *(const float4*)&As[buf][kk][ty * 4];
            float4 b0 = *(const float4*)&Bs[buf][kk][tx * 4];
            float4 b1 = *(const float4*)&Bs[buf][kk][tx * 4 + 64];
            float av[4] = {a0.x, a0.y, a0.z, a0.w};
            float bv[8] = {b0.x, b0.y, b0.z, b0.w, b1.x, b1.y, b1.z, b1.w};
#pragma unroll
            for (int i = 0; i < 4; i++)
#pragma unroll
                for (int j = 0; j < 8; j++)
                    acc[i][j] = fmaf(av[i], bv[j], acc[i][j]);
        }
        if (nxt < NCH) {
            storeAB(nxt & 1, nxt * 16);
            __syncthreads();
        }
    }

    // ---- epilogue: store output + per-thread stats accumulation ----
    float se[8], qe[8], me[8];
#pragma unroll
    for (int j = 0; j < 8; j++) { se[j] = 0.f; qe[j] = 0.f; me[j] = 0.f; }

#pragma unroll
    for (int i = 0; i < 4; i++) {
        int r = row0 + ty * 4 + i;
        int rb = AVG ? (r / Nv) : 0;
        float mk = MSUM ? mask[r] : 0.f;
#pragma unroll
        for (int jh = 0; jh < 2; jh++) {
            int c = tx * 4 + jh * 64;
            float4 o;
            o.x = acc[i][jh * 4 + 0] + bias[c + 0];
            o.y = acc[i][jh * 4 + 1] + bias[c + 1];
            o.z = acc[i][jh * 4 + 2] + bias[c + 2];
            o.w = acc[i][jh * 4 + 3] + bias[c + 3];
            if (AVG) {
                o.x += bbs[rb][c + 0];
                o.y += bbs[rb][c + 1];
                o.z += bbs[rb][c + 2];
                o.w += bbs[rb][c + 3];
            }
            if (res) {
                const float4 rv = *(const float4*)&res[(size_t)r * 128 + c];
                o.x += rv.x; o.y += rv.y; o.z += rv.z; o.w += rv.w;
            }
            *(float4*)&out[(size_t)r * 128 + c] = o;
            if (statsOut) {
                float ov[4] = {o.x, o.y, o.z, o.w};
#pragma unroll
                for (int jj = 0; jj < 4; jj++) {
                    float e = elu_f(ov[jj]);
                    int idx = jh * 4 + jj;
                    se[idx] += e;
                    qe[idx] = fmaf(e, e, qe[idx]);
                    if (MSUM) me[idx] = fmaf(mk, e, me[idx]);
                }
            }
        }
    }

    if (statsOut) {
        // reuse As/Bs as reduction scratch (mainloop done after this sync)
        float* SA = &As[0][0][0];            // 2048 floats: [16][128]
        float* SQ = &Bs[0][0][0];            // first 2048 of Bs
        float* SM = &Bs[0][0][0] + 2048;     // second 2048 of Bs
        if (MSUM && tx == 0) rbarr[ty] = (row0 + ty * 4) / Nv;
        __syncthreads();
#pragma unroll
        for (int j8 = 0; j8 < 8; j8++) {
            int c = tx * 4 + (j8 & 3) + (j8 >> 2) * 64;
            SA[ty * 128 + c] = se[j8];
            SQ[ty * 128 + c] = qe[j8];
            if (MSUM) SM[ty * 128 + c] = me[j8];
        }
        __syncthreads();
        if (tid < 128) {
            int c = tid;
            double s = 0.0, q = 0.0;
            float m0 = 0.f, m1 = 0.f;
            int rb0 = row0 / Nv;
            int rbL = (row0 + 63) / Nv;
#pragma unroll
            for (int t2 = 0; t2 < 16; t2++) {
                s += (double)SA[t2 * 128 + c];
                q += (double)SQ[t2 * 128 + c];
                if (MSUM) {
                    float mv = SM[t2 * 128 + c];
                    if (rbarr[t2] == rb0) m0 += mv; else m1 += mv;
                }
            }
            atomicAdd(&statsOut[c], s);
            atomicAdd(&statsOut[256 + c], q);
            if (MSUM) {
                atomicAdd(&amOut[rb0 * 128 + c], (double)m0);
                if (rbL != rb0) atomicAdd(&amOut[rbL * 128 + c], (double)m1);
            }
        }
    }
}

// ================= final conv =================
__global__ void final_kernel(const float* __restrict__ f,
                             const float* __restrict__ W2,
                             const float* __restrict__ b2,
                             float* __restrict__ out,
                             const double* __restrict__ stats,
                             const float* __restrict__ g2,
                             const float* __restrict__ be2) {
    __shared__ float sc[128], sh[128];
    int tid = threadIdx.x;
    if (tid < 128) {
        const double invR = 1.0 / (double)RF;
        double mean = stats[tid] * invR;
        double var  = stats[256 + tid] * invR - mean * mean;
        if (var < 0.0) var = 0.0;
        double a = (double)g2[tid] * rsqrt(var + (double)EPSV);
        sc[tid] = (float)a;
        sh[tid] = (float)((double)be2[tid] - mean * a);
    }
    __syncthreads();
    int gwarp = blockIdx.x * 8 + (tid >> 5);
    int lane = tid & 31;
    if (gwarp >= RF) return;
    float s = 0.f;
#pragma unroll
    for (int j = 0; j < 4; j++) {
        int k = lane + j * 32;
        float xh = fmaf(elu_f(f[(size_t)gwarp * 128 + k]), sc[k], sh[k]);
        s += xh * W2[k];
    }
#pragma unroll
    for (int off = 16; off; off >>= 1) s += __shfl_down_sync(0xffffffffu, s, off);
    if (lane == 0) out[gwarp] = s + b2[0];
}

// ================= host orchestration =================
extern "C" void kernel_launch(void* const* d_in, const int* in_sizes, int n_in,
                              void* d_out, int out_size) {
    const float* inputs   = (const float*)d_in[0];
    const float* mask     = (const float*)d_in[1];
    const int*   Di_rows  = (const int*)d_in[2];
    const int*   Di_cols  = (const int*)d_in[3];
    const float* Di_vals  = (const float*)d_in[4];
    const int*   DiA_rows = (const int*)d_in[5];
    const int*   DiA_cols = (const int*)d_in[6];
    const float* DiA_vals = (const float*)d_in[7];
    const float* W1       = (const float*)d_in[8];
    const float* b1       = (const float*)d_in[9];
    const float* rn_gamma = (const float*)d_in[10];
    const float* rn_beta  = (const float*)d_in[11];
    const float* rn_W     = (const float*)d_in[12];
    const float* rn_b     = (const float*)d_in[13];
    const float* g2       = (const float*)d_in[14];
    const float* be2      = (const float*)d_in[15];
    const float* W2       = (const float*)d_in[16];
    const float* b2       = (const float*)d_in[17];
    float* out = (float*)d_out;

    float *v, *f, *msg;
    double *statsL, *avgmsL;
    int *cnt, *startA, *startB;
    float2 *edgeA, *edgeB;
    cudaGetSymbolAddress((void**)&v, g_v);
    cudaGetSymbolAddress((void**)&f, g_f);
    cudaGetSymbolAddress((void**)&msg, g_msg);
    cudaGetSymbolAddress((void**)&statsL, g_statsL);
    cudaGetSymbolAddress((void**)&avgmsL, g_avgmsL);
    cudaGetSymbolAddress((void**)&cnt, g_cnt);
    cudaGetSymbolAddress((void**)&startA, g_startA);
    cudaGetSymbolAddress((void**)&startB, g_startB);
    cudaGetSymbolAddress((void**)&edgeA, g_edgeA);
    cudaGetSymbolAddress((void**)&edgeB, g_edgeB);

    auto slot = [&](int c) { return statsL + (size_t)c * 512; };

    auto build_csr = [&](const int* rows, const int* cols, const float* vals,
                         int* start, float2* edges) {
        cudaMemsetAsync(cnt, 0, BINS * sizeof(int), 0);
        hist_kernel<<<NNZ / 256, 256>>>(rows);
        scan_block_kernel<<<96, 1024>>>();
        scan_top_kernel<<<1, 32>>>();
        scan_finish_kernel<<<96, 1024>>>(start);
        fill_kernel<<<NNZ / 256, 256>>>(rows, cols, vals, edges);
    };

    // [0][1] zero stats slots
    cudaMemsetAsync(statsL, 0, 33 * 512 * sizeof(double), 0);
    cudaMemsetAsync(avgmsL, 0, 16 * 512 * sizeof(double), 0);
    // [2] conv1 (fused v-stats -> slot0 first half)
    conv1_kernel<<<RV / 64, 128>>>(inputs, W1, b1, slot(0));
    // [3][4] zero f and msg (layer-0 msg == 0; its stats stay zero)
    cudaMemsetAsync(f, 0, (size_t)RF * C * sizeof(float), 0);
    cudaMemsetAsync(msg, 0, (size_t)RV * C * sizeof(float), 0);

    const float* W0_0  = rn_W;
    // [5] layer-0 conv0 GEMM  (profiled by ncu -s 5)
    gemm_kernel<256, false, true><<<RV / 64, 256>>>(
        v, msg, W0_0, rn_b, v, v,
        slot(0), rn_gamma, rn_beta, 1.0 / RV, nullptr,
        slot(2), avgmsL, mask);

    // mask sums + CSR builds
    masksum_kernel<<<Bq, 256>>>(mask);
    build_csr(DiA_rows, DiA_cols, DiA_vals, startA, edgeA);
    build_csr(Di_rows, Di_cols, Di_vals, startB, edgeB);

    // layer-0 conv1
    spmm_kernel<<<RF / 4, 128>>>(startB, edgeB, v, Nv * C, msg, FN * C);
    statsm_kernel<<<RF / 64, 128>>>(msg, slot(1));
    gemm_kernel<256, false, false><<<RF / 64, 256>>>(
        f, msg, rn_W + 256 * 128, rn_b + 128, nullptr, f,
        slot(1), rn_gamma + 256, rn_beta + 256, 1.0 / RF, nullptr,
        slot(5), nullptr, nullptr);   // f-stats for layer-2 conv1

    for (int i = 1; i < 16; i++) {
        const float* W0  = rn_W + (size_t)i * 2 * 256 * 128;
        const float* Wb0 = rn_b + (size_t)i * 2 * 128;
        const float* gm0 = rn_gamma + (size_t)i * 2 * 256;
        const float* bt0 = rn_beta + (size_t)i * 2 * 256;

        if ((i & 1) == 0) {
            // ---- dir block ----
            spmm_kernel<<<RV / 4, 128>>>(startA, edgeA, f, FN * C, msg, Nv * C);
            statsm_kernel<<<RV / 64, 128>>>(msg, slot(2 * i));
            // v_out stats -> avg(i+1) j0 slot + am_j0
            gemm_kernel<256, false, true><<<RV / 64, 256>>>(
                v, msg, W0, Wb0, v, v,
                slot(2 * i), gm0, bt0, 1.0 / RV, nullptr,
                slot(2 * (i + 1)), avgmsL + (size_t)((i + 1) >> 1) * 2 * 512, mask);

            spmm_kernel<<<RF / 4, 128>>>(startB, edgeB, v, Nv * C, msg, FN * C);
            statsm_kernel<<<RF / 64, 128>>>(msg, slot(2 * i + 1));
            // f_out stats -> layer(i+2) conv1 slot or final slot
            double* fOut = (i == 14) ? slot(32) : slot(2 * (i + 2) + 1);
            gemm_kernel<256, false, false><<<RF / 64, 256>>>(
                f, msg, W0 + 256 * 128, Wb0 + 128, nullptr, f,
                slot(2 * i + 1), gm0 + 256, bt0 + 256, 1.0 / RF, nullptr,
                fOut, nullptr, nullptr);
        } else {
            // ---- avg block ----
            double* am0 = avgmsL + (size_t)(i >> 1) * 2 * 512;
            double* am1 = am0 + 512;

            // j0: x1 stats -> j1 slot + am_j1
            gemm_kernel<128, true, true><<<RV / 64, 256>>>(
                v, nullptr, W0, Wb0, nullptr, msg,
                slot(2 * i), gm0, bt0, 1.0 / RV, am0,
                slot(2 * i + 1), am1, mask);

            // j1: v_new stats -> next dir conv0 slot (none after layer 15)
            double* vOut = (i == 15) ? nullptr : slot(2 * (i + 1));
            gemm_kernel<128, true, false><<<RV / 64, 256>>>(
                msg, nullptr, W0 + 256 * 128, Wb0 + 128, v, v,
                slot(2 * i + 1), gm0 + 256, bt0 + 256, 1.0 / RV, am1,
                vOut, nullptr, nullptr);
        }
    }

    // final conv (stats already in slot 32 from layer-14 conv1 GEMM)
    final_kernel<<<RF / 8, 256>>>(f, W2, b2, out, slot(32), g2, be2);
}

// round 13
// speedup vs baseline: 1.7909x; 1.0883x over previous
#include <cuda_runtime.h>
#include <math.h>
#include <stdint.h>

#define Bq 4
#define Nv 12000
#define FN 24000
#define C 128
#define NNZ (48 * FN)     // 1,152,000
#define EPSV 1e-5f

#define RV (Bq * Nv)      // 48000 vertex rows
#define RF (Bq * FN)      // 96000 face rows

#define BINS 98304        // 96 * 1024 (covers 96000 rows)
#define SMEM_DYN 34880    // dynamic smem union for gemm_body

// ---------------- scratch (device globals: allocation-free) ----------------
__device__ float  g_v[RV * C];
__device__ float  g_f[RF * C];
__device__ float  g_msg[RF * C];
__device__ float  g_x1[RV * C];         // avg-block j0 output
__device__ double g_statsL[33 * 512];   // per-conv: sum[0,256), sumsq[256,512)
__device__ double g_avgmsL[16 * 512];   // per-avg-conv: masked avgsum [B][128]
__device__ double g_msum[Bq];           // per-batch mask sums

// CSR build scratch
__device__ int    g_cnt[BINS];
__device__ int    g_incl[BINS];
__device__ int    g_bsum[96];
__device__ int    g_cursor[BINS];
__device__ int    g_startA[BINS + 1];   // DiA: 48000 rows
__device__ int    g_startB[BINS + 1];   // Di : 96000 rows
__device__ float2 g_edgeA[NNZ];         // (val, bitcast col), row-sorted
__device__ float2 g_edgeB[NNZ];

__device__ __forceinline__ float elu_f(float x) {
    return x > 0.f ? x : expm1f(x);
}

// ================= CSR build =================
__global__ void hist_kernel(const int* __restrict__ rows) {
    int i = blockIdx.x * blockDim.x + threadIdx.x;
    if (i < NNZ) atomicAdd(&g_cnt[rows[i]], 1);
}

__global__ void scan_block_kernel() {
    __shared__ int sd[1024];
    int t = threadIdx.x;
    int gid = blockIdx.x * 1024 + t;
    sd[t] = g_cnt[gid];
    __syncthreads();
    for (int off = 1; off < 1024; off <<= 1) {
        int add = (t >= off) ? sd[t - off] : 0;
        __syncthreads();
        sd[t] += add;
        __syncthreads();
    }
    g_incl[gid] = sd[t];
    if (t == 1023) g_bsum[blockIdx.x] = sd[1023];
}

__global__ void scan_top_kernel() {
    if (threadIdx.x == 0) {
        int run = 0;
        for (int b = 0; b < 96; b++) { int tt = g_bsum[b]; g_bsum[b] = run; run += tt; }
    }
}

__global__ void scan_finish_kernel(int* __restrict__ start) {
    int t = threadIdx.x;
    int gid = blockIdx.x * 1024 + t;
    int excl = g_incl[gid] - g_cnt[gid] + g_bsum[blockIdx.x];
    start[gid] = excl;
    g_cursor[gid] = excl;
    if (gid == BINS - 1) start[BINS] = excl + g_cnt[gid];
}

__global__ void fill_kernel(const int* __restrict__ rows,
                            const int* __restrict__ cols,
                            const float* __restrict__ vals,
                            float2* __restrict__ edges) {
    int i = blockIdx.x * blockDim.x + threadIdx.x;
    if (i >= NNZ) return;
    int pos = atomicAdd(&g_cursor[rows[i]], 1);
    edges[pos] = make_float2(vals[i], __int_as_float(cols[i]));
}

// ================= SpMM (CSR, atomic-free) =================
__global__ void spmm_kernel(const int* __restrict__ start,
                            const float2* __restrict__ edges,
                            const float* __restrict__ in, int inStride,
                            float* __restrict__ out, int outStride) {
    int t = threadIdx.x;
    int r = blockIdx.x * 4 + (t >> 5);
    int lane = t & 31;
    int b = lane >> 3, k4 = lane & 7;
    int s = start[r], e = start[r + 1];
    float4 acc = make_float4(0.f, 0.f, 0.f, 0.f);
    const float* inb = in + (size_t)b * inStride;
    for (int i = s; i < e; i++) {
        float2 ed = edges[i];
        int c = __float_as_int(ed.y);
        float4 q = *(const float4*)&inb[c * 32 + k4 * 4];
        acc.x = fmaf(ed.x, q.x, acc.x);
        acc.y = fmaf(ed.x, q.y, acc.y);
        acc.z = fmaf(ed.x, q.z, acc.z);
        acc.w = fmaf(ed.x, q.w, acc.w);
    }
    *(float4*)&out[(size_t)b * outStride + r * 32 + k4 * 4] = acc;
}

// 256-thread SpMM body for fused launches (8 rows per block)
__device__ void spmm_body(int bid, const int* __restrict__ start,
                          const float2* __restrict__ edges,
                          const float* __restrict__ in, int inStride,
                          float* __restrict__ out, int outStride) {
    int r = bid * 8 + (threadIdx.x >> 5);
    int lane = threadIdx.x & 31;
    int b = lane >> 3, k4 = lane & 7;
    int s = start[r], e = start[r + 1];
    float4 acc = make_float4(0.f, 0.f, 0.f, 0.f);
    const float* inb = in + (size_t)b * inStride;
    for (int i = s; i < e; i++) {
        float2 ed = edges[i];
        int c = __float_as_int(ed.y);
        float4 q = *(const float4*)&inb[c * 32 + k4 * 4];
        acc.x = fmaf(ed.x, q.x, acc.x);
        acc.y = fmaf(ed.x, q.y, acc.y);
        acc.z = fmaf(ed.x, q.z, acc.z);
        acc.w = fmaf(ed.x, q.w, acc.w);
    }
    *(float4*)&out[(size_t)b * outStride + r * 32 + k4 * 4] = acc;
}

// ================= conv1 (fused stats -> slot0 first half) =================
__global__ void conv1_kernel(const float* __restrict__ in,
                             const float* __restrict__ W1,
                             const float* __restrict__ b1,
                             double* __restrict__ st) {
    int c = threadIdx.x;                  // 128
    int r0 = blockIdx.x * 64;
    float w0 = W1[c], w1 = W1[128 + c], w2 = W1[256 + c], bb = b1[c];
    float s = 0.f, q = 0.f;
    for (int i = 0; i < 64; i++) {
        int r = r0 + i;
        float x0 = in[r * 3 + 0], x1 = in[r * 3 + 1], x2 = in[r * 3 + 2];
        float val = fmaf(x0, w0, fmaf(x1, w1, fmaf(x2, w2, bb)));
        g_v[(size_t)r * 128 + c] = val;
        float e = elu_f(val);
        s += e; q += e * e;
    }
    atomicAdd(&st[c], (double)s);
    atomicAdd(&st[256 + c], (double)q);
}

// ================= slim stats over msg (second-half channels) =================
__global__ void statsm_kernel(const float* __restrict__ x,
                              double* __restrict__ st) {
    int c = threadIdx.x;                  // 128
    int r0 = blockIdx.x * 64;
    float s = 0.f, q = 0.f;
    for (int i = 0; i < 64; i++) {
        float e = elu_f(x[(size_t)(r0 + i) * 128 + c]);
        s += e; q += e * e;
    }
    atomicAdd(&st[128 + c], (double)s);
    atomicAdd(&st[384 + c], (double)q);
}

// ================= per-batch mask sums (once per replay) =================
__global__ void masksum_kernel(const float* __restrict__ mask) {
    __shared__ float sd[256];
    int b = blockIdx.x, t = threadIdx.x;
    float s = 0.f;
    for (int i = t; i < Nv; i += 256) s += mask[b * Nv + i];
    sd[t] = s;
    __syncthreads();
    for (int off = 128; off; off >>= 1) {
        if (t < off) sd[t] += sd[t + off];
        __syncthreads();
    }
    if (t == 0) g_msum[b] = (double)sd[0];
}

// ================= GEMM body: 64x128 tile, 256 threads =================
// Dynamic smem union layout (SMEM_DYN bytes):
//   As   [0,8192)      2 x 16 x 64 f32
//   Bs   [8192,24576)  2 x 16 x 128 f32
//   sc   [24576,25600) sh [25600,26624)
//   xh2s [26624,28672) bbp [28672,32768) bbs [32768,34816) rbarr [34816,34880)
template <int KD, bool AVG, bool MSUM>
__device__ void gemm_body(
    int bid,
    const float* __restrict__ A0, const float* __restrict__ A1,
    const float* __restrict__ W, const float* __restrict__ bias,
    const float* __restrict__ res, float* __restrict__ out,
    const double* __restrict__ stats,
    const float* __restrict__ gamma, const float* __restrict__ beta,
    double invR, const double* __restrict__ avgms,
    double* __restrict__ statsOut, double* __restrict__ amOut,
    const float* __restrict__ mask) {
    extern __shared__ char sm[];
    float* As   = (float*)sm;                  // [buf*16+kl]*64 + arow
    float* Bs   = (float*)(sm + 8192);         // [buf*16+kk]*128 + col
    float* sc   = (float*)(sm + 24576);
    float* sh   = (float*)(sm + 25600);
    float* xh2s = (float*)(sm + 26624);        // [b*128+k]
    float* bbp  = (float*)(sm + 28672);        // [(h*4+b)*128+c]
    float* bbs  = (float*)(sm + 32768);        // [b*128+c]
    int*   rbarr = (int*)(sm + 34816);
    const int tid = threadIdx.x;
    const int row0 = bid * 64;

    // ---- prologue: BN scale/shift from stats slot ----
    if (tid < KD) {
        double mean = stats[tid] * invR;
        double var  = stats[256 + tid] * invR - mean * mean;
        if (var < 0.0) var = 0.0;
        double a = (double)gamma[tid] * rsqrt(var + (double)EPSV);
        sc[tid] = (float)a;
        sh[tid] = (float)((double)beta[tid] - mean * a);
    }
    if (AVG && tid < 128) {
        float af[Bq];
        double s = 0.0, sq = 0.0;
        for (int b = 0; b < Bq; b++) {
            af[b] = (float)(avgms[b * 128 + tid] / g_msum[b]);
            double m = (double)af[b];
            s  += m * (double)Nv;
            sq += m * m * (double)Nv;
        }
        double mean = s * (1.0 / (double)RV);
        double var  = sq * (1.0 / (double)RV) - mean * mean;
        if (var < 0.0) var = 0.0;
        double a = (double)gamma[128 + tid] * rsqrt(var + (double)EPSV);
        float sck = (float)a;
        float shk = (float)((double)beta[128 + tid] - mean * a);
#pragma unroll
        for (int b = 0; b < Bq; b++) xh2s[b * 128 + tid] = fmaf(af[b], sck, shk);
    }

    const int arow = tid & 63;
    const int ksg  = (tid >> 6) * 4;
    const int bkr  = tid >> 4;
    const int bcx  = (tid & 15) * 4;
    const int ty = tid >> 4, tx = tid & 15;
    const int NCH = KD / 16;

    float4 areg, breg[2];

    auto loadAB = [&](int k0) {
        int k = k0 + ksg;
        const float* src;
        if (KD == 256 && k >= 128)
            src = A1 + (size_t)(row0 + arow) * 128 + (k - 128);
        else
            src = A0 + (size_t)(row0 + arow) * 128 + k;
        areg = *(const float4*)src;
#pragma unroll
        for (int q = 0; q < 2; q++)
            breg[q] = *(const float4*)&W[(size_t)(k0 + bkr) * 128 + bcx + q * 64];
    };
    auto storeAB = [&](int buf, int k0) {
        float vv[4] = {areg.x, areg.y, areg.z, areg.w};
#pragma unroll
        for (int j = 0; j < 4; j++) {
            int kl = ksg + j;
            float x = vv[j];
            x = x > 0.f ? x : expm1f(x);
            As[(buf * 16 + kl) * 64 + arow] = fmaf(x, sc[k0 + kl], sh[k0 + kl]);
        }
#pragma unroll
        for (int q = 0; q < 2; q++)
            *(float4*)&Bs[(buf * 16 + bkr) * 128 + bcx + q * 64] = breg[q];
    };

    float acc[4][8];
#pragma unroll
    for (int i = 0; i < 4; i++)
#pragma unroll
        for (int j = 0; j < 8; j++) acc[i][j] = 0.f;

    loadAB(0);
    __syncthreads();            // sc/sh (+xh2s) ready

    if (AVG) {
        // bb fold: bb[b][c] = sum_kk xh2[b][kk] * W[(128+kk)*128 + c]
        int c = tid & 127, h = tid >> 7;
        float p0 = 0.f, p1 = 0.f, p2 = 0.f, p3 = 0.f;
        for (int kk = h * 64; kk < h * 64 + 64; kk++) {
            float w = W[(size_t)(128 + kk) * 128 + c];
            p0 = fmaf(xh2s[0 * 128 + kk], w, p0);
            p1 = fmaf(xh2s[1 * 128 + kk], w, p1);
            p2 = fmaf(xh2s[2 * 128 + kk], w, p2);
            p3 = fmaf(xh2s[3 * 128 + kk], w, p3);
        }
        bbp[(h * 4 + 0) * 128 + c] = p0; bbp[(h * 4 + 1) * 128 + c] = p1;
        bbp[(h * 4 + 2) * 128 + c] = p2; bbp[(h * 4 + 3) * 128 + c] = p3;
        __syncthreads();
        if (tid < 128) {
#pragma unroll
            for (int b = 0; b < Bq; b++)
                bbs[b * 128 + tid] = bbp[(0 * 4 + b) * 128 + tid]
                                   + bbp[(1 * 4 + b) * 128 + tid];
        }
    }

    storeAB(0, 0);
    __syncthreads();

    for (int ch = 0; ch < NCH; ch++) {
        int nxt = ch + 1;
        if (nxt < NCH) loadAB(nxt * 16);
        int buf = ch & 1;
#pragma unroll
        for (int kk = 0; kk < 16; kk++) {
            float4 a0 = *(const float4*)&As[(buf * 16 + kk) * 64 + ty * 4];
            float4 b0 = *(const float4*)&Bs[(buf * 16 + kk) * 128 + tx * 4];
            float4 b1 = *(const float4*)&Bs[(buf * 16 + kk) * 128 + tx * 4 + 64];
            float av[4] = {a0.x, a0.y, a0.z, a0.w};
            float bv[8] = {b0.x, b0.y, b0.z, b0.w, b1.x, b1.y, b1.z, b1.w};
#pragma unroll
            for (int i = 0; i < 4; i++)
#pragma unroll
                for (int j = 0; j < 8; j++)
                    acc[i][j] = fmaf(av[i], bv[j], acc[i][j]);
        }
        if (nxt < NCH) {
            storeAB(nxt & 1, nxt * 16);
            __syncthreads();
        }
    }

    // ---- epilogue: store output + per-thread stats accumulation ----
    float se[8], qe[8], me[8];
#pragma unroll
    for (int j = 0; j < 8; j++) { se[j] = 0.f; qe[j] = 0.f; me[j] = 0.f; }

#pragma unroll
    for (int i = 0; i < 4; i++) {
        int r = row0 + ty * 4 + i;
        int rb = AVG ? (r / Nv) : 0;
        float mk = MSUM ? mask[r] : 0.f;
#pragma unroll
        for (int jh = 0; jh < 2; jh++) {
            int c = tx * 4 + jh * 64;
            float4 o;
            o.x = acc[i][jh * 4 + 0] + bias[c + 0];
            o.y = acc[i][jh * 4 + 1] + bias[c + 1];
            o.z = acc[i][jh * 4 + 2] + bias[c + 2];
            o.w = acc[i][jh * 4 + 3] + bias[c + 3];
            if (AVG) {
                o.x += bbs[rb * 128 + c + 0];
                o.y += bbs[rb * 128 + c + 1];
                o.z += bbs[rb * 128 + c + 2];
                o.w += bbs[rb * 128 + c + 3];
            }
            if (res) {
                const float4 rv = *(const float4*)&res[(size_t)r * 128 + c];
                o.x += rv.x; o.y += rv.y; o.z += rv.z; o.w += rv.w;
            }
            *(float4*)&out[(size_t)r * 128 + c] = o;
            if (statsOut) {
                float ov[4] = {o.x, o.y, o.z, o.w};
#pragma unroll
                for (int jj = 0; jj < 4; jj++) {
                    float e = elu_f(ov[jj]);
                    int idx = jh * 4 + jj;
                    se[idx] += e;
                    qe[idx] = fmaf(e, e, qe[idx]);
                    if (MSUM) me[idx] = fmaf(mk, e, me[idx]);
                }
            }
        }
    }

    if (statsOut) {
        // reuse As/Bs as reduction scratch (mainloop done after this sync)
        float* SA = As;                      // 2048 floats: [16][128]
        float* SQ = Bs;                      // first 2048 of Bs
        float* SM = Bs + 2048;               // second 2048 of Bs
        if (MSUM && tx == 0) rbarr[ty] = (row0 + ty * 4) / Nv;
        __syncthreads();
#pragma unroll
        for (int j8 = 0; j8 < 8; j8++) {
            int c = tx * 4 + (j8 & 3) + (j8 >> 2) * 64;
            SA[ty * 128 + c] = se[j8];
            SQ[ty * 128 + c] = qe[j8];
            if (MSUM) SM[ty * 128 + c] = me[j8];
        }
        __syncthreads();
        if (tid < 128) {
            int c = tid;
            double s = 0.0, q = 0.0;
            float m0 = 0.f, m1 = 0.f;
            int rb0 = row0 / Nv;
            int rbL = (row0 + 63) / Nv;
#pragma unroll
            for (int t2 = 0; t2 < 16; t2++) {
                s += (double)SA[t2 * 128 + c];
                q += (double)SQ[t2 * 128 + c];
                if (MSUM) {
                    float mv = SM[t2 * 128 + c];
                    if (rbarr[t2] == rb0) m0 += mv; else m1 += mv;
                }
            }
            atomicAdd(&statsOut[c], s);
            atomicAdd(&statsOut[256 + c], q);
            if (MSUM) {
                atomicAdd(&amOut[rb0 * 128 + c], (double)m0);
                if (rbL != rb0) atomicAdd(&amOut[rbL * 128 + c], (double)m1);
            }
        }
    }
}

// ---- standalone GEMM wrappers ----
template <int KD, bool AVG, bool MSUM>
__global__ void __launch_bounds__(256, 3) gemm_kernel(
    const float* A0, const float* A1, const float* W, const float* bias,
    const float* res, float* out, const double* stats,
    const float* gamma, const float* beta, double invR, const double* avgms,
    double* statsOut, double* amOut, const float* mask) {
    gemm_body<KD, AVG, MSUM>(blockIdx.x, A0, A1, W, bias, res, out, stats,
                             gamma, beta, invR, avgms, statsOut, amOut, mask);
}

// ---- FUSED: dir conv1 GEMM (blocks [0,nb1)) + avg j0 GEMM (rest) ----
__global__ void __launch_bounds__(256, 3) fused_g1j0_kernel(
    // dir conv1 (KD=256)
    const float* f, const float* msg, const float* Wc1, const float* bc1,
    const double* st_c1, const float* gm_c1, const float* bt_c1,
    double* stOut_c1,
    // avg j0 (KD=128, AVG, MSUM)
    const float* v, float* x1, const float* Wj0, const float* bj0,
    const double* st_j0, const float* gm_j0, const float* bt_j0,
    const double* am0, double* st_j1, double* am1, const float* mask,
    int nb1) {
    if (blockIdx.x < nb1) {
        gemm_body<256, false, false>(blockIdx.x, f, msg, Wc1, bc1, nullptr,
                                     (float*)f, st_c1, gm_c1, bt_c1,
                                     1.0 / RF, nullptr, stOut_c1, nullptr,
                                     nullptr);
    } else {
        gemm_body<128, true, true>(blockIdx.x - nb1, v, nullptr, Wj0, bj0,
                                   nullptr, x1, st_j0, gm_j0, bt_j0,
                                   1.0 / RV, am0, st_j1, am1, mask);
    }
}

// ---- FUSED: avg j1 GEMM (blocks [0,nb1)) + next-layer spmmA (rest) ----
__global__ void __launch_bounds__(256, 3) fused_j1spmm_kernel(
    // avg j1 (KD=128, AVG)
    const float* x1, float* v, const float* Wj1, const float* bj1,
    const double* st_j1, const float* gm_j1, const float* bt_j1,
    const double* am1, double* stOut_v,
    // spmmA: msg = DiA @ f
    const int* startA, const float2* edgeA, const float* f, float* msg,
    int nb1) {
    if (blockIdx.x < nb1) {
        gemm_body<128, true, false>(blockIdx.x, x1, nullptr, Wj1, bj1, v, v,
                                    st_j1, gm_j1, bt_j1, 1.0 / RV, am1,
                                    stOut_v, nullptr, nullptr);
    } else {
        spmm_body(blockIdx.x - nb1, startA, edgeA, f, FN * C, msg, Nv * C);
    }
}

// ================= final conv =================
__global__ void final_kernel(const float* __restrict__ f,
                             const float* __restrict__ W2,
                             const float* __restrict__ b2,
                             float* __restrict__ out,
                             const double* __restrict__ stats,
                             const float* __restrict__ g2,
                             const float* __restrict__ be2) {
    __shared__ float sc[128], sh[128];
    int tid = threadIdx.x;
    if (tid < 128) {
        const double invR = 1.0 / (double)RF;
        double mean = stats[tid] * invR;
        double var  = stats[256 + tid] * invR - mean * mean;
        if (var < 0.0) var = 0.0;
        double a = (double)g2[tid] * rsqrt(var + (double)EPSV);
        sc[tid] = (float)a;
        sh[tid] = (float)((double)be2[tid] - mean * a);
    }
    __syncthreads();
    int gwarp = blockIdx.x * 8 + (tid >> 5);
    int lane = tid & 31;
    if (gwarp >= RF) return;
    float s = 0.f;
#pragma unroll
    for (int j = 0; j < 4; j++) {
        int k = lane + j * 32;
        float xh = fmaf(elu_f(f[(size_t)gwarp * 128 + k]), sc[k], sh[k]);
        s += xh * W2[k];
    }
#pragma unroll
    for (int off = 16; off; off >>= 1) s += __shfl_down_sync(0xffffffffu, s, off);
    if (lane == 0) out[gwarp] = s + b2[0];
}

// ================= host orchestration =================
extern "C" void kernel_launch(void* const* d_in, const int* in_sizes, int n_in,
                              void* d_out, int out_size) {
    const float* inputs   = (const float*)d_in[0];
    const float* mask     = (const float*)d_in[1];
    const int*   Di_rows  = (const int*)d_in[2];
    const int*   Di_cols  = (const int*)d_in[3];
    const float* Di_vals  = (const float*)d_in[4];
    const int*   DiA_rows = (const int*)d_in[5];
    const int*   DiA_cols = (const int*)d_in[6];
    const float* DiA_vals = (const float*)d_in[7];
    const float* W1       = (const float*)d_in[8];
    const float* b1       = (const float*)d_in[9];
    const float* rn_gamma = (const float*)d_in[10];
    const float* rn_beta  = (const float*)d_in[11];
    const float* rn_W     = (const float*)d_in[12];
    const float* rn_b     = (const float*)d_in[13];
    const float* g2       = (const float*)d_in[14];
    const float* be2      = (const float*)d_in[15];
    const float* W2       = (const float*)d_in[16];
    const float* b2       = (const float*)d_in[17];
    float* out = (float*)d_out;

    float *v, *f, *msg, *x1;
    double *statsL, *avgmsL;
    int *cnt, *startA, *startB;
    float2 *edgeA, *edgeB;
    cudaGetSymbolAddress((void**)&v, g_v);
    cudaGetSymbolAddress((void**)&f, g_f);
    cudaGetSymbolAddress((void**)&msg, g_msg);
    cudaGetSymbolAddress((void**)&x1, g_x1);
    cudaGetSymbolAddress((void**)&statsL, g_statsL);
    cudaGetSymbolAddress((void**)&avgmsL, g_avgmsL);
    cudaGetSymbolAddress((void**)&cnt, g_cnt);
    cudaGetSymbolAddress((void**)&startA, g_startA);
    cudaGetSymbolAddress((void**)&startB, g_startB);
    cudaGetSymbolAddress((void**)&edgeA, g_edgeA);
    cudaGetSymbolAddress((void**)&edgeB, g_edgeB);

    auto slot = [&](int c) { return statsL + (size_t)c * 512; };

    auto build_csr = [&](const int* rows, const int* cols, const float* vals,
                         int* start, float2* edges) {
        cudaMemsetAsync(cnt, 0, BINS * sizeof(int), 0);
        hist_kernel<<<NNZ / 256, 256>>>(rows);
        scan_block_kernel<<<96, 1024>>>();
        scan_top_kernel<<<1, 32>>>();
        scan_finish_kernel<<<96, 1024>>>(start);
        fill_kernel<<<NNZ / 256, 256>>>(rows, cols, vals, edges);
    };

    // prologue
    cudaMemsetAsync(statsL, 0, 33 * 512 * sizeof(double), 0);
    cudaMemsetAsync(avgmsL, 0, 16 * 512 * sizeof(double), 0);
    conv1_kernel<<<RV / 64, 128>>>(inputs, W1, b1, slot(0));
    cudaMemsetAsync(f, 0, (size_t)RF * C * sizeof(float), 0);
    cudaMemsetAsync(msg, 0, (size_t)RV * C * sizeof(float), 0);
    masksum_kernel<<<Bq, 256>>>(mask);
    build_csr(DiA_rows, DiA_cols, DiA_vals, startA, edgeA);
    build_csr(Di_rows, Di_cols, Di_vals, startB, edgeB);

    // pairs p: dir layer d = 2p, avg layer a = 2p+1
    for (int p = 0; p < 8; p++) {
        int d = 2 * p;
        const float* Wd  = rn_W + (size_t)d * 2 * 256 * 128;
        const float* bd  = rn_b + (size_t)d * 2 * 128;
        const float* gmd = rn_gamma + (size_t)d * 2 * 256;
        const float* btd = rn_beta + (size_t)d * 2 * 256;
        const float* Wa  = rn_W + (size_t)(d + 1) * 2 * 256 * 128;
        const float* ba  = rn_b + (size_t)(d + 1) * 2 * 128;
        const float* gma = rn_gamma + (size_t)(d + 1) * 2 * 256;
        const float* bta = rn_beta + (size_t)(d + 1) * 2 * 256;
        double* am0 = avgmsL + (size_t)p * 1024;
        double* am1 = am0 + 512;

        // dir conv0 (msg from previous fused spmmA; p=0: msg==0, stats zero)
        if (p > 0) statsm_kernel<<<RV / 64, 128>>>(msg, slot(2 * d));
        gemm_kernel<256, false, true><<<RV / 64, 256, SMEM_DYN>>>(
            v, msg, Wd, bd, v, v,
            slot(2 * d), gmd, btd, 1.0 / RV, nullptr,
            slot(2 * d + 2), am0, mask);

        // dir conv1 inputs
        spmm_kernel<<<RF / 4, 128>>>(startB, edgeB, v, Nv * C, msg, FN * C);
        statsm_kernel<<<RF / 64, 128>>>(msg, slot(2 * d + 1));

        // FUSED: dir conv1 GEMM (f) + avg j0 GEMM (x1)
        double* fOut = (p == 7) ? slot(32) : slot(2 * (d + 2) + 1);
        fused_g1j0_kernel<<<RF / 64 + RV / 64, 256, SMEM_DYN>>>(
            f, msg, Wd + 256 * 128, bd + 128,
            slot(2 * d + 1), gmd + 256, btd + 256, fOut,
            v, x1, Wa, ba,
            slot(2 * d + 2), gma, bta,
            am0, slot(2 * d + 3), am1, mask,
            RF / 64);

        if (p < 7) {
            // FUSED: avg j1 GEMM (v) + next dir's spmmA (msg)
            fused_j1spmm_kernel<<<RV / 64 + RV / 8, 256, SMEM_DYN>>>(
                x1, v, Wa + 256 * 128, ba + 128,
                slot(2 * d + 3), gma + 256, bta + 256,
                am1, slot(2 * d + 4),
                startA, edgeA, f, msg,
                RV / 64);
        } else {
            gemm_kernel<128, true, false><<<RV / 64, 256, SMEM_DYN>>>(
                x1, nullptr, Wa + 256 * 128, ba + 128, v, v,
                slot(2 * d + 3), gma + 256, bta + 256, 1.0 / RV, am1,
                nullptr, nullptr, nullptr);
        }
    }

    // final conv (stats in slot 32 from pair-7 dir conv1)
    final_kernel<<<RF / 8, 256>>>(f, W2, b2, out, slot(32), g2, be2);
}